// round 13
// baseline (speedup 1.0000x reference)
#include <cuda_runtime.h>
#include <cuda_bf16.h>
#include <math.h>
#include <stdint.h>

#define S_LEN 40
#define T_LEN 30
#define BB    64
#define EMBD  620
#define HIDN  1000
#define ATTD  1000
#define MXO   500
#define OUTV  30000
#define G3    3000
#define E2    2000
#define DXK   2620
#define MXK   3620
#define MX2   1000

// windows (32 K-cols each) per operand family
#define NW_EX  20      // K=620  -> Kp 640
#define NW_WH  32      // K=1000 -> 1024
#define NW_EN  64      // K=2000 -> 2048
#define NW_X   82      // K=2620 -> 2624
#define NW_MI  114     // K=3620 -> 3648
#define NW_TM  16      // K=500  -> 512

#define TILE_E 4096            // bf16 elems per 8KB tile (128 rows x 32 cols)
#define TILE_B 8192

// ---------------- fp32 workspace ----------------
static const size_t O_GXF = 0;
static const size_t O_GXB = O_GXF + (size_t)S_LEN*BB*G3;
static const size_t O_ENC = O_GXB + (size_t)S_LEN*BB*G3;
static const size_t O_EP  = O_ENC + (size_t)S_LEN*BB*E2;
static const size_t O_PA  = O_EP  + (size_t)S_LEN*BB*ATTD;
static const size_t O_PB  = O_PA  + (size_t)8*BB*G3;
static const size_t O_PM  = O_PB  + (size_t)8*BB*G3;
static const size_t O_HF  = O_PM  + (size_t)8*BB*MX2;
static const size_t O_HB  = O_HF  + (size_t)BB*HIDN;
static const size_t O_HD  = O_HB  + (size_t)BB*HIDN;
static const size_t ARENA = O_HD  + (size_t)BB*HIDN;

__device__ __align__(256) float g_ws[ARENA];
__device__ unsigned long long g_amax[BB];

// ---------------- tiled bf16 weight arena (tile = 8KB smem image) ---------
static const size_t WB_EXF = 0;
static const size_t WB_EXB = WB_EXF + (size_t)24*NW_EX*3*TILE_E;
static const size_t WB_WHF = WB_EXB + (size_t)24*NW_EX*3*TILE_E;
static const size_t WB_WHB = WB_WHF + (size_t)24*NW_WH*3*TILE_E;
static const size_t WB_FC  = WB_WHB + (size_t)24*NW_WH*3*TILE_E;
static const size_t WB_AWH = WB_FC  + (size_t)8*NW_WH*3*TILE_E;
static const size_t WB_AWE = WB_AWH + (size_t)8*NW_WH*3*TILE_E;
static const size_t WB_DWX = WB_AWE + (size_t)8*NW_EN*3*TILE_E;
static const size_t WB_DWH = WB_DWX + (size_t)24*NW_X*3*TILE_E;
static const size_t WB_MXW = WB_DWH + (size_t)24*NW_WH*3*TILE_E;
static const size_t WB_OUW = WB_MXW + (size_t)8*NW_MI*3*TILE_E;
static const size_t WB_TOT = WB_OUW + (size_t)235*NW_TM*3*TILE_E;

__device__ __align__(256) __nv_bfloat16 g_wb[WB_TOT];

// ---------------- tiled bf16 activation arena ----------------
static const size_t AB_EMB = 0;
static const size_t AB_ENC = AB_EMB + (size_t)20*NW_EX*3*TILE_E;
static const size_t AB_HF  = AB_ENC + (size_t)20*NW_EN*3*TILE_E;
static const size_t AB_HB  = AB_HF  + (size_t)NW_WH*3*TILE_E;
static const size_t AB_HD  = AB_HB  + (size_t)NW_WH*3*TILE_E;
static const size_t AB_X   = AB_HD  + (size_t)NW_WH*3*TILE_E;
static const size_t AB_MI  = AB_X   + (size_t)NW_X*3*TILE_E;
static const size_t AB_TM  = AB_MI  + (size_t)NW_MI*3*TILE_E;
static const size_t AB_TOT = AB_TM  + (size_t)NW_TM*3*TILE_E;

__device__ __align__(256) __nv_bfloat16 g_ab[AB_TOT];

// ---------------- helpers ----------------
__device__ __forceinline__ uint32_t su32(const void* p)
{
    uint32_t a;
    asm("{ .reg .u64 t; cvta.to.shared.u64 t, %1; cvt.u32.u64 %0, t; }"
        : "=r"(a) : "l"(p));
    return a;
}
// SW64 descriptor: layout=4, version=1 (Blackwell), SBO=32 (512B = 8 rows x 64B), LBO=1
__device__ __forceinline__ uint64_t mkdesc(uint32_t addr)
{
    const uint64_t base = (uint64_t(4) << 61) | (uint64_t(1) << 46) |
                          (uint64_t(32) << 32) | (uint64_t(1) << 16);
    return base | ((uint64_t)(addr >> 4) & 0x3FFF);
}
__device__ __forceinline__ void mbar_init(uint32_t mb, uint32_t cnt)
{
    asm volatile("mbarrier.init.shared.b64 [%0], %1;" :: "r"(mb), "r"(cnt) : "memory");
}
__device__ __forceinline__ void mbar_wait(uint32_t mb, int parity)
{
    asm volatile(
        "{\n\t.reg .pred P;\n\t"
        "WL_%=:\n\t"
        "mbarrier.try_wait.parity.acquire.cta.shared::cta.b64 P, [%0], %1, 0x989680;\n\t"
        "@P bra.uni WD_%=;\n\t"
        "bra.uni WL_%=;\n\t"
        "WD_%=:\n\t}"
        :: "r"(mb), "r"(parity) : "memory");
}
__device__ __forceinline__ void expect_tx(uint32_t mb, uint32_t bytes)
{
    asm volatile("mbarrier.arrive.expect_tx.shared.b64 _, [%0], %1;"
                 :: "r"(mb), "r"(bytes) : "memory");
}
__device__ __forceinline__ void bulk_g2s(uint32_t dst, const void* src, uint32_t mb)
{
    asm volatile(
        "cp.async.bulk.shared::cluster.global.mbarrier::complete_tx::bytes [%0], [%1], %2, [%3];"
        :: "r"(dst), "l"(src), "r"((uint32_t)TILE_B), "r"(mb) : "memory");
}
__device__ __forceinline__ void mma_bf16_ss(uint32_t d, uint64_t ad, uint64_t bd,
                                            uint32_t idesc, uint32_t acc)
{
    asm volatile(
        "{\n\t.reg .pred p;\n\t"
        "setp.ne.u32 p, %5, 0;\n\t"
        "tcgen05.mma.cta_group::1.kind::f16 [%0], %1, %2, %3, {%4,%4,%4,%4}, p;\n\t}"
        :: "r"(d), "l"(ad), "l"(bd), "r"(idesc), "r"(0u), "r"(acc) : "memory");
}
__device__ __forceinline__ void tc_commit(uint32_t mb)
{
    asm volatile(
        "tcgen05.commit.cta_group::1.mbarrier::arrive::one.shared::cluster.b64 [%0];"
        :: "r"(mb) : "memory");
}
#define LDTM_X32(r, ta) \
    asm volatile( \
        "tcgen05.ld.sync.aligned.32x32b.x32.b32 " \
        "{%0,%1,%2,%3,%4,%5,%6,%7,%8,%9,%10,%11,%12,%13,%14,%15," \
        "%16,%17,%18,%19,%20,%21,%22,%23,%24,%25,%26,%27,%28,%29,%30,%31}, [%32];" \
        : "=r"((r)[0]),"=r"((r)[1]),"=r"((r)[2]),"=r"((r)[3]), \
          "=r"((r)[4]),"=r"((r)[5]),"=r"((r)[6]),"=r"((r)[7]), \
          "=r"((r)[8]),"=r"((r)[9]),"=r"((r)[10]),"=r"((r)[11]), \
          "=r"((r)[12]),"=r"((r)[13]),"=r"((r)[14]),"=r"((r)[15]), \
          "=r"((r)[16]),"=r"((r)[17]),"=r"((r)[18]),"=r"((r)[19]), \
          "=r"((r)[20]),"=r"((r)[21]),"=r"((r)[22]),"=r"((r)[23]), \
          "=r"((r)[24]),"=r"((r)[25]),"=r"((r)[26]),"=r"((r)[27]), \
          "=r"((r)[28]),"=r"((r)[29]),"=r"((r)[30]),"=r"((r)[31]) \
        : "r"(ta))

#define TG_IDESC 0x8200490u
// double-buffered: 2 x (3A + 3B) x 8KB = 96KB => still 2 CTAs/SM
#define TG_SMEM  (1024 + 12 * TILE_B)

// tiled offset (bf16 elems): tile = 128 rows x 32 cols, 64B rows, SW64 swizzle
__device__ __forceinline__ size_t toff(int nwin, int R, int k)
{
    uint32_t inner = (uint32_t)((R & 127) * 64 + (k & 31) * 2);
    inner ^= (inner >> 3) & 0x30;
    return ((size_t)(((R >> 7) * nwin + (k >> 5)) * 3) << 12) + (inner >> 1);
}
__device__ __forceinline__ void wsplit3_t(__nv_bfloat16* base, int nwin, int R, int k, float a)
{
    __nv_bfloat16 h = __float2bfloat16(a);
    float r1 = a - __bfloat162float(h);
    __nv_bfloat16 m = __float2bfloat16(r1);
    float r2 = r1 - __bfloat162float(m);
    size_t o = toff(nwin, R, k);
    base[o] = h;
    base[o + TILE_E] = m;
    base[o + 2 * TILE_E] = __float2bfloat16(r2);
}
__device__ __forceinline__ unsigned long long amax_key(float v, int idx)
{
    unsigned u = __float_as_uint(v);
    u = (u & 0x80000000u) ? ~u : (u | 0x80000000u);
    return ((unsigned long long)u << 32) | (unsigned)(OUTV - idx);
}

// ---------------- weight conversion ----------------
__global__ void wconv_k(const float* __restrict__ W, int rs, int co,
                        __nv_bfloat16* __restrict__ Wb, int N, int K, int nwin)
{
    const int Kp = nwin * 32;
    const int NT = (N + 127) >> 7;
    const size_t tot = (size_t)NT * 128 * Kp;
    size_t i = (size_t)blockIdx.x * blockDim.x + threadIdx.x;
    if (i >= tot) return;
    int R = (int)(i / Kp), k = (int)(i - (size_t)R * Kp);
    float a = (R < N && k < K) ? W[(size_t)R * rs + co + k] : 0.f;
    wsplit3_t(Wb, nwin, R, k, a);
}

// ---------------------------------------------------------------------------
// tcgen05 GEMM: TMA-bulk staged, DOUBLE-buffered 32-col windows,
// 2 CTAs/SM. One CTA = one (tile, split) unit. amax=1: fused argmax.
// ---------------------------------------------------------------------------
struct TG {
    const __nv_bfloat16* Ab;
    const __nv_bfloat16* Wb;
    const float* bias;
    float* C;
    int M, N, nwin, split, amax;
};

__global__ void __launch_bounds__(128) tgemm_k(TG g0, TG g1, int ua)
{
#if defined(__CUDA_ARCH_FEAT_SM103_ALL)
    const int u = blockIdx.x;
    const TG g = (u < ua) ? g0 : g1;
    int v = (u < ua) ? u : u - ua;
    const int ntn = (g.N + 127) >> 7;
    const int z = v % g.split;
    const int rest = v / g.split;
    const int nt = rest % ntn;
    const int mt = rest / ntn;
    const int nwin = g.nwin;
    const int kcw = (nwin + g.split - 1) / g.split;
    const int w0 = z * kcw;
    int w1 = w0 + kcw; if (w1 > nwin) w1 = nwin;
    const int nw = (w1 > w0) ? (w1 - w0) : 0;
    const int m0 = mt << 7, n0 = nt << 7;
    const bool fin = (g.split == 1);
    float* Cz = g.C + (size_t)z * g.M * g.N;

    const int tid = threadIdx.x;
    const int wid = tid >> 5, lane = tid & 31;

    extern __shared__ __align__(16) char dyn[];
    const uint32_t dbase = (su32(dyn) + 1023u) & ~1023u;

    __shared__ __align__(8) unsigned long long s_bar[4];  // ld0 ld1 mm0 mm1
    __shared__ uint32_t s_tptr;

    if (wid == 0) {
        asm volatile("tcgen05.alloc.cta_group::1.sync.aligned.shared::cta.b32 [%0], %1;"
                     :: "r"(su32(&s_tptr)), "r"(128u) : "memory");
        asm volatile("tcgen05.relinquish_alloc_permit.cta_group::1.sync.aligned;");
    }
    if (tid == 0)
        for (int i = 0; i < 4; i++) mbar_init(su32(&s_bar[i]), 1);
    __syncthreads();
    const uint32_t tmem = s_tptr;

    if (nw > 0 && tid == 0) {
        const uint32_t ld[2] = {su32(&s_bar[0]), su32(&s_bar[1])};
        const uint32_t mm[2] = {su32(&s_bar[2]), su32(&s_bar[3])};
        int pl[2] = {0, 0}, pq[2] = {0, 0};
        const char* At = (const char*)g.Ab;
        const char* Bt = (const char*)g.Wb;
        const int segA[6] = {0, 1, 2, 0, 1, 0};
        const int segB[6] = {0, 0, 0, 1, 1, 2};
        bool first = true;

        for (int i = 0; i < nw; i++) {
            const int buf = i & 1;
            const int w = w0 + i;
            if (i >= 2) { mbar_wait(mm[buf], pq[buf]); pq[buf] ^= 1; }
            expect_tx(ld[buf], 6u * TILE_B);
            const size_t abase = ((size_t)((mt * nwin + w) * 3)) * TILE_B;
            const size_t bbase = ((size_t)((nt * nwin + w) * 3)) * TILE_B;
#pragma unroll
            for (int p = 0; p < 3; p++) {
                bulk_g2s(dbase + (uint32_t)(buf * 6 + p) * TILE_B,
                         At + abase + (size_t)p * TILE_B, ld[buf]);
                bulk_g2s(dbase + (uint32_t)(buf * 6 + 3 + p) * TILE_B,
                         Bt + bbase + (size_t)p * TILE_B, ld[buf]);
            }
            mbar_wait(ld[buf], pl[buf]); pl[buf] ^= 1;
#pragma unroll
            for (int s = 0; s < 6; s++) {
                uint64_t ad = mkdesc(dbase + (uint32_t)(buf * 6 + segA[s]) * TILE_B);
                uint64_t bd = mkdesc(dbase + (uint32_t)(buf * 6 + 3 + segB[s]) * TILE_B);
#pragma unroll
                for (int q = 0; q < 2; q++) {
                    mma_bf16_ss(tmem, ad + 2 * q, bd + 2 * q, TG_IDESC, first ? 0u : 1u);
                    first = false;
                }
            }
            tc_commit(mm[buf]);
        }
        for (int t = (nw >= 2 ? nw - 2 : 0); t < nw; t++) {
            const int buf = t & 1;
            mbar_wait(mm[buf], pq[buf]); pq[buf] ^= 1;
        }
    }
    __syncthreads();
    asm volatile("tcgen05.fence::after_thread_sync;" ::: "memory");

    // epilogue
    const int r = m0 + wid * 32 + lane;
    if (nw == 0) {
        if (r < g.M)
            for (int c0 = 0; c0 < 128; c0++) {
                int c = n0 + c0;
                if (c < g.N) Cz[(size_t)r * g.N + c] = (fin && g.bias) ? g.bias[c] : 0.f;
            }
    } else {
        float bestv = -1e30f; int besti = 0;
#pragma unroll
        for (int base = 0; base < 128; base += 32) {
            uint32_t regs[32];
            LDTM_X32(regs, tmem + base);
            asm volatile("tcgen05.wait::ld.sync.aligned;" ::: "memory");
            if (r < g.M) {
#pragma unroll
                for (int q = 0; q < 32; q++) {
                    int c = n0 + base + q;
                    if (c < g.N) {
                        float vv = __uint_as_float(regs[q]);
                        if (fin && g.bias) vv += g.bias[c];
                        Cz[(size_t)r * g.N + c] = vv;
                        if (g.amax && (vv > bestv || (vv == bestv && c < besti))) {
                            bestv = vv; besti = c;
                        }
                    }
                }
            }
        }
        if (g.amax && r < g.M)
            atomicMax(&g_amax[r], amax_key(bestv, besti));
    }
    __syncthreads();
    if (wid == 0)
        asm volatile("tcgen05.dealloc.cta_group::1.sync.aligned.b32 %0, %1;"
                     :: "r"(tmem), "r"(128u));
#else
    (void)g0; (void)g1; (void)ua;   // compile-only stub (runtime picks sm_103a cubin)
#endif
}

// ---------------- elementwise / fused kernels ----------------
__global__ void embed_split_k(const float* __restrict__ table, const int* __restrict__ idx,
                              __nv_bfloat16* __restrict__ Ab)
{
    int i = blockIdx.x * blockDim.x + threadIdx.x;
    if (i >= S_LEN * BB * EMBD) return;
    int r = i / EMBD, e = i - r * EMBD;
    wsplit3_t(Ab, NW_EX, r, e, table[(size_t)idx[r] * EMBD + e]);
}

__global__ void gru_gate2_k(const float* __restrict__ gxf, const float* __restrict__ gxb,
                            const float* __restrict__ pf, const float* __restrict__ pb,
                            const float* __restrict__ bhf, const float* __restrict__ bhb,
                            float* __restrict__ hf, float* __restrict__ hb,
                            __nv_bfloat16* __restrict__ Ahf,
                            __nv_bfloat16* __restrict__ Ahb,
                            float* __restrict__ enc,
                            __nv_bfloat16* __restrict__ Aenc,
                            int sf, int sb)
{
    int i = blockIdx.x * blockDim.x + threadIdx.x;
    if (i >= 2 * BB * HIDN) return;
    int dir = (i >= BB * HIDN);
    int ii = dir ? i - BB * HIDN : i;
    int b = ii / HIDN, j = ii - b * HIDN;
    const float* gx = (dir ? gxb : gxf) + (size_t)b * G3;
    const float* phh = dir ? pb : pf;
    const float* bh = dir ? bhb : bhf;
    float* h = dir ? hb : hf;

    float xr = gx[j], xz = gx[HIDN + j], xn = gx[2 * HIDN + j];
    float hr = bh[j], hz = bh[HIDN + j], hn = bh[2 * HIDN + j];
    for (int z = 0; z < 4; z++) {
        const float* q = phh + ((size_t)z * BB + b) * G3;
        hr += q[j]; hz += q[HIDN + j]; hn += q[2 * HIDN + j];
    }
    float r  = 1.f / (1.f + expf(-(xr + hr)));
    float zz = 1.f / (1.f + expf(-(xz + hz)));
    float n  = tanhf(xn + r * hn);
    float h2 = (1.f - zz) * n + zz * h[ii];
    h[ii] = h2;
    wsplit3_t(dir ? Ahb : Ahf, NW_WH, b, j, h2);
    int row = (dir ? sb : sf) * BB + b;
    int col = dir ? HIDN + j : j;
    enc[(size_t)row * E2 + col] = h2;
    wsplit3_t(Aenc, NW_EN, row, col, h2);
}

__global__ void finalize_tanh_hd_k(const float* __restrict__ parts,
                                   const float* __restrict__ bias,
                                   float* __restrict__ hd,
                                   __nv_bfloat16* __restrict__ Ahd)
{
    int i = blockIdx.x * blockDim.x + threadIdx.x;
    if (i >= BB * HIDN) return;
    int b = i / HIDN, j = i - b * HIDN;
    float v = 0.f;
    for (int z = 0; z < 8; z++) v += parts[(size_t)z * BB * HIDN + i];
    v = tanhf(v + bias[j]);
    hd[i] = v;
    wsplit3_t(Ahd, NW_WH, b, j, v);
}

// fused attention: token from trg (t==0) or fused argmax of previous step
__global__ void attention_k(const float* __restrict__ pa,
                            const float* __restrict__ ep,
                            const float* __restrict__ ab,
                            const float* __restrict__ av,
                            const float* __restrict__ enc,
                            const float* __restrict__ demb,
                            const int*   __restrict__ trg, int t,
                            __nv_bfloat16* __restrict__ Ax,
                            __nv_bfloat16* __restrict__ Ami)
{
    const int b = blockIdx.x;
    const int tid = threadIdx.x;
    const int wid = tid >> 5, lane = tid & 31;
    __shared__ float hqs[ATTD];
    __shared__ float al[S_LEN];

    for (int a = tid; a < ATTD; a += 256) {
        float s = 0.f;
#pragma unroll
        for (int z = 0; z < 8; z++) s += pa[((size_t)z * BB + b) * ATTD + a];
        hqs[a] = s;
    }
    __syncthreads();

    for (int s = wid; s < S_LEN; s += 8) {
        const float* eprow = ep + ((size_t)s * BB + b) * ATTD;
        float e = 0.f;
        for (int a = lane; a < ATTD; a += 32)
            e += av[a] * tanhf(hqs[a] + eprow[a] + ab[a]);
#pragma unroll
        for (int o = 16; o; o >>= 1) e += __shfl_down_sync(0xffffffffu, e, o);
        if (lane == 0) al[s] = e;
    }
    __syncthreads();

    if (tid == 0) {
        float m = -1e30f;
        for (int s = 0; s < S_LEN; s++) m = fmaxf(m, al[s]);
        float sum = 0.f;
        for (int s = 0; s < S_LEN; s++) { float e = expf(al[s] - m); al[s] = e; sum += e; }
        float inv = 1.f / sum;
        for (int s = 0; s < S_LEN; s++) al[s] *= inv;
    }
    __syncthreads();

    for (int hc = tid; hc < E2; hc += 256) {
        float c = 0.f;
        for (int s = 0; s < S_LEN; s++)
            c += al[s] * enc[((size_t)s * BB + b) * E2 + hc];
        wsplit3_t(Ax, NW_X, b, EMBD + hc, c);
        wsplit3_t(Ami, NW_MI, b, HIDN + hc, c);
    }
    const int tok = (t == 0) ? trg[b]
                  : (int)(OUTV - (unsigned)(g_amax[b] & 0xffffffffu));
    for (int e = tid; e < EMBD; e += 256) {
        float vv = demb[(size_t)tok * EMBD + e];
        wsplit3_t(Ax, NW_X, b, e, vv);
        wsplit3_t(Ami, NW_MI, b, G3 + e, vv);
    }
}

__global__ void gru_gate_k(const float* __restrict__ gx, const float* __restrict__ bx,
                           const float* __restrict__ gh, const float* __restrict__ bh,
                           float* __restrict__ h,
                           __nv_bfloat16* __restrict__ Ahd,
                           __nv_bfloat16* __restrict__ Ami)
{
    int i = blockIdx.x * blockDim.x + threadIdx.x;
    if (i >= BB * HIDN) return;
    int b = i / HIDN, j = i - b * HIDN;
    float xr = bx[j], xz = bx[HIDN + j], xn = bx[2 * HIDN + j];
    float hr = bh[j], hz = bh[HIDN + j], hn = bh[2 * HIDN + j];
    for (int z = 0; z < 4; z++) {
        const float* q1 = gx + ((size_t)z * BB + b) * G3;
        const float* q2 = gh + ((size_t)z * BB + b) * G3;
        xr += q1[j]; xz += q1[HIDN + j]; xn += q1[2 * HIDN + j];
        hr += q2[j]; hz += q2[HIDN + j]; hn += q2[2 * HIDN + j];
    }
    float r  = 1.f / (1.f + expf(-(xr + hr)));
    float zz = 1.f / (1.f + expf(-(xz + hz)));
    float n  = tanhf(xn + r * hn);
    float h2 = (1.f - zz) * n + zz * h[i];
    h[i] = h2;
    wsplit3_t(Ahd, NW_WH, b, j, h2);
    wsplit3_t(Ami, NW_MI, b, j, h2);
}

// maxout finalize + zero the argmax accumulator for this step's vocab GEMM
__global__ void finalize_max_k(const float* __restrict__ pm,
                               const float* __restrict__ bias,
                               __nv_bfloat16* __restrict__ Atm)
{
    int i = blockIdx.x * blockDim.x + threadIdx.x;
    if (i < BB) g_amax[i] = 0ull;
    if (i >= BB * MXO) return;
    int b = i / MXO, o = i - b * MXO;
    float v0 = bias[2 * o], v1 = bias[2 * o + 1];
    for (int z = 0; z < 8; z++) {
        const float* q = pm + ((size_t)z * BB + b) * MX2;
        v0 += q[2 * o]; v1 += q[2 * o + 1];
    }
    wsplit3_t(Atm, NW_TM, b, o, fmaxf(v0, v1));
}

// ---------------- host ----------------
static inline int up(int n, int b) { return (n + b - 1) / b; }

static inline TG mkt(const __nv_bfloat16* Ab, const __nv_bfloat16* Wb,
                     const float* bias, float* C, int M, int N, int nwin,
                     int split, int amax = 0)
{
    TG g; g.Ab = Ab; g.Wb = Wb; g.bias = bias; g.C = C;
    g.M = M; g.N = N; g.nwin = nwin; g.split = split; g.amax = amax;
    return g;
}
static inline int units(const TG& g)
{
    return ((g.M + 127) >> 7) * ((g.N + 127) >> 7) * g.split;
}
static inline void tg1(const TG& g)
{
    tgemm_k<<<units(g), 128, TG_SMEM>>>(g, g, units(g));
}
static inline void tg2(const TG& a, const TG& b)
{
    tgemm_k<<<units(a) + units(b), 128, TG_SMEM>>>(a, b, units(a));
}
static inline void wconv(const float* W, int rs, int co,
                         __nv_bfloat16* Wb, int N, int K, int nwin)
{
    int NT = (N + 127) >> 7;
    size_t tot = (size_t)NT * 128 * nwin * 32;
    wconv_k<<<(unsigned)((tot + 255) / 256), 256>>>(W, rs, co, Wb, N, K, nwin);
}

extern "C" void kernel_launch(void* const* d_in, const int* in_sizes, int n_in,
                              void* d_out, int out_size)
{
    (void)in_sizes; (void)n_in; (void)out_size;
    const int*   src      = (const int*)  d_in[0];
    const int*   trg      = (const int*)  d_in[1];
    const float* enc_emb  = (const float*)d_in[2];
    const float* enc_wx_f = (const float*)d_in[3];
    const float* enc_wh_f = (const float*)d_in[4];
    const float* enc_bx_f = (const float*)d_in[5];
    const float* enc_bh_f = (const float*)d_in[6];
    const float* enc_wx_b = (const float*)d_in[7];
    const float* enc_wh_b = (const float*)d_in[8];
    const float* enc_bx_b = (const float*)d_in[9];
    const float* enc_bh_b = (const float*)d_in[10];
    const float* enc_fc_w = (const float*)d_in[11];
    const float* enc_fc_b = (const float*)d_in[12];
    const float* attn_w   = (const float*)d_in[13];
    const float* attn_b   = (const float*)d_in[14];
    const float* attn_v   = (const float*)d_in[15];
    const float* dec_emb  = (const float*)d_in[16];
    const float* dec_wx   = (const float*)d_in[17];
    const float* dec_wh   = (const float*)d_in[18];
    const float* dec_bx   = (const float*)d_in[19];
    const float* dec_bh   = (const float*)d_in[20];
    const float* max_w    = (const float*)d_in[21];
    const float* max_b    = (const float*)d_in[22];
    const float* out_w    = (const float*)d_in[23];
    const float* out_b    = (const float*)d_in[24];

    cudaFuncSetAttribute(tgemm_k, cudaFuncAttributeMaxDynamicSharedMemorySize, TG_SMEM);

    float* ws = nullptr;
    __nv_bfloat16* wb = nullptr; __nv_bfloat16* abx = nullptr;
    cudaGetSymbolAddress((void**)&ws, g_ws);
    cudaGetSymbolAddress((void**)&wb, g_wb);
    cudaGetSymbolAddress((void**)&abx, g_ab);

    float* gxf = ws + O_GXF;
    float* gxb = ws + O_GXB;
    float* enc = ws + O_ENC;
    float* ep  = ws + O_EP;
    float* pa  = ws + O_PA;
    float* pb  = ws + O_PB;
    float* pm  = ws + O_PM;
    float* hf  = ws + O_HF;
    float* hb  = ws + O_HB;
    float* hd  = ws + O_HD;
    float* out = (float*)d_out;

    __nv_bfloat16* Aemb = abx + AB_EMB;
    __nv_bfloat16* Aenc = abx + AB_ENC;
    __nv_bfloat16* Ahf  = abx + AB_HF;
    __nv_bfloat16* Ahb  = abx + AB_HB;
    __nv_bfloat16* Ahd  = abx + AB_HD;
    __nv_bfloat16* Ax   = abx + AB_X;
    __nv_bfloat16* Ami  = abx + AB_MI;
    __nv_bfloat16* Atm  = abx + AB_TM;

    // weight conversion (tiled)
    wconv(enc_wx_f, EMBD, 0,    wb + WB_EXF, 3000, EMBD, NW_EX);
    wconv(enc_wx_b, EMBD, 0,    wb + WB_EXB, 3000, EMBD, NW_EX);
    wconv(enc_wh_f, HIDN, 0,    wb + WB_WHF, 3000, HIDN, NW_WH);
    wconv(enc_wh_b, HIDN, 0,    wb + WB_WHB, 3000, HIDN, NW_WH);
    wconv(enc_fc_w, HIDN, 0,    wb + WB_FC,  1000, HIDN, NW_WH);
    wconv(attn_w,   G3,   0,    wb + WB_AWH, 1000, HIDN, NW_WH);
    wconv(attn_w,   G3,   HIDN, wb + WB_AWE, 1000, E2,   NW_EN);
    wconv(dec_wx,   DXK,  0,    wb + WB_DWX, 3000, DXK,  NW_X);
    wconv(dec_wh,   HIDN, 0,    wb + WB_DWH, 3000, HIDN, NW_WH);
    wconv(max_w,    MXK,  0,    wb + WB_MXW, 1000, MXK,  NW_MI);
    wconv(out_w,    MXO,  0,    wb + WB_OUW, 30000, MXO, NW_TM);

    cudaMemsetAsync(abx, 0, AB_TOT * sizeof(__nv_bfloat16));
    cudaMemsetAsync(hf, 0, (size_t)2 * BB * HIDN * sizeof(float));  // hf+hb adjacent
    cudaMemsetAsync(out, 0, (size_t)BB * OUTV * sizeof(float));

    // ---------------- Encoder ----------------
    embed_split_k<<<up(S_LEN * BB * EMBD, 256), 256>>>(enc_emb, src, Aemb);
    tg2(mkt(Aemb, wb + WB_EXF, enc_bx_f, gxf, S_LEN * BB, G3, NW_EX, 1),
        mkt(Aemb, wb + WB_EXB, enc_bx_b, gxb, S_LEN * BB, G3, NW_EX, 1));

    for (int s = 0; s < S_LEN; s++) {
        int sb = S_LEN - 1 - s;
        tg2(mkt(Ahf, wb + WB_WHF, nullptr, pa, BB, G3, NW_WH, 4),
            mkt(Ahb, wb + WB_WHB, nullptr, pb, BB, G3, NW_WH, 4));
        gru_gate2_k<<<up(2 * BB * HIDN, 256), 256>>>(
            gxf + (size_t)s * BB * G3, gxb + (size_t)sb * BB * G3,
            pa, pb, enc_bh_f, enc_bh_b, hf, hb, Ahf, Ahb, enc, Aenc, s, sb);
    }

    tg1(mkt(Ahb, wb + WB_FC, nullptr, pa, BB, HIDN, NW_WH, 8));
    finalize_tanh_hd_k<<<up(BB * HIDN, 256), 256>>>(pa, enc_fc_b, hd, Ahd);
    // e_part + initial hq (dual)
    tg2(mkt(Aenc, wb + WB_AWE, nullptr, ep, S_LEN * BB, ATTD, NW_EN, 1),
        mkt(Ahd, wb + WB_AWH, nullptr, pa, BB, ATTD, NW_WH, 8));

    // ---------------- Decoder ----------------
    for (int t = 0; t < T_LEN - 1; t++) {
        attention_k<<<BB, 256>>>(pa, ep, attn_b, attn_v, enc, dec_emb, trg, t, Ax, Ami);
        tg2(mkt(Ax,  wb + WB_DWX, nullptr, pa, BB, G3, NW_X,  4),
            mkt(Ahd, wb + WB_DWH, nullptr, pb, BB, G3, NW_WH, 4));
        gru_gate_k<<<up(BB * HIDN, 256), 256>>>(pa, dec_bx, pb, dec_bh, hd, Ahd, Ami);
        // maxout GEMM + next-step hq GEMM (dual); hq writes pa (free after gate)
        tg2(mkt(Ami, wb + WB_MXW, nullptr, pm, BB, MX2, NW_MI, 8),
            mkt(Ahd, wb + WB_AWH, nullptr, pa, BB, ATTD, NW_WH, 8));
        finalize_max_k<<<up(BB * MXO, 256), 256>>>(pm, max_b, Atm);
        float* pred = out + (size_t)(t + 1) * BB * OUTV;
        tg1(mkt(Atm, wb + WB_OUW, out_b, pred, BB, OUTV, NW_TM, 1, 1));
    }
}

// round 14
// speedup vs baseline: 1.0213x; 1.0213x over previous
#include <cuda_runtime.h>
#include <cuda_bf16.h>
#include <math.h>
#include <stdint.h>

#define S_LEN 40
#define T_LEN 30
#define BB    64
#define EMBD  620
#define HIDN  1000
#define ATTD  1000
#define MXO   500
#define OUTV  30000
#define G3    3000
#define E2    2000
#define DXK   2620
#define MXK   3620
#define MX2   1000

// windows (64 K-cols each) per operand family
#define NW_EX  10
#define NW_WH  16
#define NW_EN  32
#define NW_X   41
#define NW_MI  57
#define NW_TM  8

#define TILE_E 8192
#define TILE_B 16384

// ---------------- fp32 workspace ----------------
static const size_t O_GXF = 0;
static const size_t O_GXB = O_GXF + (size_t)S_LEN*BB*G3;
static const size_t O_ENC = O_GXB + (size_t)S_LEN*BB*G3;
static const size_t O_EP  = O_ENC + (size_t)S_LEN*BB*E2;
static const size_t O_PA  = O_EP  + (size_t)S_LEN*BB*ATTD;
static const size_t O_PB  = O_PA  + (size_t)8*BB*G3;
static const size_t O_PM  = O_PB  + (size_t)8*BB*G3;
static const size_t O_HF  = O_PM  + (size_t)8*BB*MX2;
static const size_t O_HB  = O_HF  + (size_t)BB*HIDN;
static const size_t O_HD  = O_HB  + (size_t)BB*HIDN;
static const size_t ARENA = O_HD  + (size_t)BB*HIDN;

__device__ __align__(256) float g_ws[ARENA];
__device__ unsigned long long g_amax[BB];

// ---------------- tiled bf16 weight arena (tile = 16KB smem image) --------
static const size_t WB_EXF = 0;
static const size_t WB_EXB = WB_EXF + (size_t)24*NW_EX*3*TILE_E;
static const size_t WB_WHF = WB_EXB + (size_t)24*NW_EX*3*TILE_E;
static const size_t WB_WHB = WB_WHF + (size_t)24*NW_WH*3*TILE_E;
static const size_t WB_FC  = WB_WHB + (size_t)24*NW_WH*3*TILE_E;
static const size_t WB_AWH = WB_FC  + (size_t)8*NW_WH*3*TILE_E;
static const size_t WB_AWE = WB_AWH + (size_t)8*NW_WH*3*TILE_E;
static const size_t WB_DWX = WB_AWE + (size_t)8*NW_EN*3*TILE_E;
static const size_t WB_DWH = WB_DWX + (size_t)24*NW_X*3*TILE_E;
static const size_t WB_MXW = WB_DWH + (size_t)24*NW_WH*3*TILE_E;
static const size_t WB_OUW = WB_MXW + (size_t)8*NW_MI*3*TILE_E;
static const size_t WB_TOT = WB_OUW + (size_t)235*NW_TM*3*TILE_E;

__device__ __align__(256) __nv_bfloat16 g_wb[WB_TOT];

// ---------------- tiled bf16 activation arena ----------------
static const size_t AB_EMB = 0;
static const size_t AB_ENC = AB_EMB + (size_t)20*NW_EX*3*TILE_E;
static const size_t AB_HF  = AB_ENC + (size_t)20*NW_EN*3*TILE_E;
static const size_t AB_HB  = AB_HF  + (size_t)NW_WH*3*TILE_E;
static const size_t AB_HD  = AB_HB  + (size_t)NW_WH*3*TILE_E;
static const size_t AB_X   = AB_HD  + (size_t)NW_WH*3*TILE_E;
static const size_t AB_MI  = AB_X   + (size_t)NW_X*3*TILE_E;
static const size_t AB_TM  = AB_MI  + (size_t)NW_MI*3*TILE_E;
static const size_t AB_TOT = AB_TM  + (size_t)NW_TM*3*TILE_E;

__device__ __align__(256) __nv_bfloat16 g_ab[AB_TOT];

// ---------------- PDL: trigger at top, wait BEFORE any global access ------
#define GDC_LAUNCH() asm volatile("griddepcontrol.launch_dependents;")
#define GDC_WAIT()   asm volatile("griddepcontrol.wait;" ::: "memory")

// ---------------- helpers ----------------
__device__ __forceinline__ uint32_t su32(const void* p)
{
    uint32_t a;
    asm("{ .reg .u64 t; cvta.to.shared.u64 t, %1; cvt.u32.u64 %0, t; }"
        : "=r"(a) : "l"(p));
    return a;
}
__device__ __forceinline__ uint64_t mkdesc(uint32_t addr)
{
    const uint64_t base = (uint64_t(2) << 61) | (uint64_t(1) << 46) |
                          (uint64_t(64) << 32) | (uint64_t(1) << 16);
    return base | ((uint64_t)(addr >> 4) & 0x3FFF);
}
__device__ __forceinline__ void mbar_init(uint32_t mb, uint32_t cnt)
{
    asm volatile("mbarrier.init.shared.b64 [%0], %1;" :: "r"(mb), "r"(cnt) : "memory");
}
__device__ __forceinline__ void mbar_wait(uint32_t mb, int parity)
{
    asm volatile(
        "{\n\t.reg .pred P;\n\t"
        "WL_%=:\n\t"
        "mbarrier.try_wait.parity.acquire.cta.shared::cta.b64 P, [%0], %1, 0x989680;\n\t"
        "@P bra.uni WD_%=;\n\t"
        "bra.uni WL_%=;\n\t"
        "WD_%=:\n\t}"
        :: "r"(mb), "r"(parity) : "memory");
}
__device__ __forceinline__ void expect_tx(uint32_t mb, uint32_t bytes)
{
    asm volatile("mbarrier.arrive.expect_tx.shared.b64 _, [%0], %1;"
                 :: "r"(mb), "r"(bytes) : "memory");
}
__device__ __forceinline__ void bulk_g2s(uint32_t dst, const void* src, uint32_t mb)
{
    asm volatile(
        "cp.async.bulk.shared::cluster.global.mbarrier::complete_tx::bytes [%0], [%1], %2, [%3];"
        :: "r"(dst), "l"(src), "r"((uint32_t)TILE_B), "r"(mb) : "memory");
}
__device__ __forceinline__ void mma_bf16_ss(uint32_t d, uint64_t ad, uint64_t bd,
                                            uint32_t idesc, uint32_t acc)
{
    asm volatile(
        "{\n\t.reg .pred p;\n\t"
        "setp.ne.u32 p, %5, 0;\n\t"
        "tcgen05.mma.cta_group::1.kind::f16 [%0], %1, %2, %3, {%4,%4,%4,%4}, p;\n\t}"
        :: "r"(d), "l"(ad), "l"(bd), "r"(idesc), "r"(0u), "r"(acc) : "memory");
}
__device__ __forceinline__ void tc_commit(uint32_t mb)
{
    asm volatile(
        "tcgen05.commit.cta_group::1.mbarrier::arrive::one.shared::cluster.b64 [%0];"
        :: "r"(mb) : "memory");
}
#define LDTM_X32(r, ta) \
    asm volatile( \
        "tcgen05.ld.sync.aligned.32x32b.x32.b32 " \
        "{%0,%1,%2,%3,%4,%5,%6,%7,%8,%9,%10,%11,%12,%13,%14,%15," \
        "%16,%17,%18,%19,%20,%21,%22,%23,%24,%25,%26,%27,%28,%29,%30,%31}, [%32];" \
        : "=r"((r)[0]),"=r"((r)[1]),"=r"((r)[2]),"=r"((r)[3]), \
          "=r"((r)[4]),"=r"((r)[5]),"=r"((r)[6]),"=r"((r)[7]), \
          "=r"((r)[8]),"=r"((r)[9]),"=r"((r)[10]),"=r"((r)[11]), \
          "=r"((r)[12]),"=r"((r)[13]),"=r"((r)[14]),"=r"((r)[15]), \
          "=r"((r)[16]),"=r"((r)[17]),"=r"((r)[18]),"=r"((r)[19]), \
          "=r"((r)[20]),"=r"((r)[21]),"=r"((r)[22]),"=r"((r)[23]), \
          "=r"((r)[24]),"=r"((r)[25]),"=r"((r)[26]),"=r"((r)[27]), \
          "=r"((r)[28]),"=r"((r)[29]),"=r"((r)[30]),"=r"((r)[31]) \
        : "r"(ta))

#define TG_IDESC 0x8200490u
// single-buffered: 6 tiles -> 97KB => 2 CTAs/SM co-resident
#define TG_SMEM  (1024 + 6 * TILE_B)

__device__ __forceinline__ size_t toff(int nwin, int R, int k)
{
    uint32_t inner = (uint32_t)((R & 127) * 128 + (k & 63) * 2);
    inner ^= (inner >> 3) & 0x70;
    return ((size_t)(((R >> 7) * nwin + (k >> 6)) * 3) << 13) + (inner >> 1);
}
__device__ __forceinline__ void wsplit3_t(__nv_bfloat16* base, int nwin, int R, int k, float a)
{
    __nv_bfloat16 h = __float2bfloat16(a);
    float r1 = a - __bfloat162float(h);
    __nv_bfloat16 m = __float2bfloat16(r1);
    float r2 = r1 - __bfloat162float(m);
    size_t o = toff(nwin, R, k);
    base[o] = h;
    base[o + TILE_E] = m;
    base[o + 2 * TILE_E] = __float2bfloat16(r2);
}
__device__ __forceinline__ unsigned long long amax_key(float v, int idx)
{
    unsigned u = __float_as_uint(v);
    u = (u & 0x80000000u) ? ~u : (u | 0x80000000u);
    return ((unsigned long long)u << 32) | (unsigned)(OUTV - idx);
}

// ---------------- weight conversion (no parent dependency: no wait) -------
__global__ void wconv_k(const float* __restrict__ W, int rs, int co,
                        __nv_bfloat16* __restrict__ Wb, int N, int K, int nwin)
{
    GDC_LAUNCH();
    const int Kp = nwin * 64;
    const int NT = (N + 127) >> 7;
    const size_t tot = (size_t)NT * 128 * Kp;
    size_t i = (size_t)blockIdx.x * blockDim.x + threadIdx.x;
    if (i >= tot) return;
    int R = (int)(i / Kp), k = (int)(i - (size_t)R * Kp);
    float a = (R < N && k < K) ? W[(size_t)R * rs + co + k] : 0.f;
    wsplit3_t(Wb, nwin, R, k, a);
}

// ---------------------------------------------------------------------------
// tcgen05 GEMM, TMA-bulk staged, single-buffered (2 CTAs/SM overlap).
// PDL: CTAs resident + TMEM/mbar prologue pre-wait; ALL global access
// strictly after griddepcontrol.wait (no eager prefetch).
// ---------------------------------------------------------------------------
struct TG {
    const __nv_bfloat16* Ab;
    const __nv_bfloat16* Wb;
    const float* bias;
    float* C;
    int M, N, nwin, split, amax;
};

__global__ void __launch_bounds__(128) tgemm_k(TG g0, TG g1, int ua)
{
#if defined(__CUDA_ARCH_FEAT_SM103_ALL)
    GDC_LAUNCH();
    const int u = blockIdx.x;
    const TG g = (u < ua) ? g0 : g1;
    int v = (u < ua) ? u : u - ua;
    const int ntn = (g.N + 127) >> 7;
    const int z = v % g.split;
    const int rest = v / g.split;
    const int nt = rest % ntn;
    const int mt = rest / ntn;
    const int nwin = g.nwin;
    const int kcw = (nwin + g.split - 1) / g.split;
    const int w0 = z * kcw;
    int w1 = w0 + kcw; if (w1 > nwin) w1 = nwin;
    const int nw = (w1 > w0) ? (w1 - w0) : 0;
    const int m0 = mt << 7, n0 = nt << 7;
    const bool fin = (g.split == 1);
    float* Cz = g.C + (size_t)z * g.M * g.N;

    const int tid = threadIdx.x;
    const int wid = tid >> 5, lane = tid & 31;

    extern __shared__ __align__(16) char dyn[];
    const uint32_t dbase = (su32(dyn) + 1023u) & ~1023u;

    __shared__ __align__(8) unsigned long long s_bar[2];  // ld, mm
    __shared__ uint32_t s_tptr;

    if (wid == 0) {
        asm volatile("tcgen05.alloc.cta_group::1.sync.aligned.shared::cta.b32 [%0], %1;"
                     :: "r"(su32(&s_tptr)), "r"(128u) : "memory");
        asm volatile("tcgen05.relinquish_alloc_permit.cta_group::1.sync.aligned;");
    }
    if (tid == 0) { mbar_init(su32(&s_bar[0]), 1); mbar_init(su32(&s_bar[1]), 1); }
    __syncthreads();
    const uint32_t tmem = s_tptr;

    if (tid == 0) GDC_WAIT();   // parent done: safe to read activations/weights

    if (nw > 0 && tid == 0) {
        const uint32_t ld = su32(&s_bar[0]);
        const uint32_t mm = su32(&s_bar[1]);
        int pl = 0, pq = 0;
        const char* At = (const char*)g.Ab;
        const char* Bt = (const char*)g.Wb;
        const int segA[6] = {0, 1, 2, 0, 1, 0};
        const int segB[6] = {0, 0, 0, 1, 1, 2};
        bool first = true;

        for (int i = 0; i < nw; i++) {
            const int w = w0 + i;
            expect_tx(ld, 6u * TILE_B);
            const size_t abase = ((size_t)((mt * nwin + w) * 3)) * TILE_B;
            const size_t bbase = ((size_t)((nt * nwin + w) * 3)) * TILE_B;
#pragma unroll
            for (int p = 0; p < 3; p++) {
                bulk_g2s(dbase + (uint32_t)p * TILE_B, At + abase + (size_t)p * TILE_B, ld);
                bulk_g2s(dbase + (uint32_t)(3 + p) * TILE_B, Bt + bbase + (size_t)p * TILE_B, ld);
            }
            mbar_wait(ld, pl); pl ^= 1;
#pragma unroll
            for (int s = 0; s < 6; s++) {
                uint64_t ad = mkdesc(dbase + (uint32_t)segA[s] * TILE_B);
                uint64_t bd = mkdesc(dbase + (uint32_t)(3 + segB[s]) * TILE_B);
#pragma unroll
                for (int q = 0; q < 4; q++) {
                    mma_bf16_ss(tmem, ad + 2 * q, bd + 2 * q, TG_IDESC, first ? 0u : 1u);
                    first = false;
                }
            }
            tc_commit(mm);
            mbar_wait(mm, pq); pq ^= 1;   // single buffer: drain before reuse
        }
    }
    __syncthreads();
    asm volatile("tcgen05.fence::after_thread_sync;" ::: "memory");

    // epilogue
    const int r = m0 + wid * 32 + lane;
    if (nw == 0) {
        if (r < g.M)
            for (int c0 = 0; c0 < 128; c0++) {
                int c = n0 + c0;
                if (c < g.N) Cz[(size_t)r * g.N + c] = (fin && g.bias) ? g.bias[c] : 0.f;
            }
    } else {
        float bestv = -1e30f; int besti = 0;
#pragma unroll
        for (int base = 0; base < 128; base += 32) {
            uint32_t regs[32];
            LDTM_X32(regs, tmem + base);
            asm volatile("tcgen05.wait::ld.sync.aligned;" ::: "memory");
            if (r < g.M) {
#pragma unroll
                for (int q = 0; q < 32; q++) {
                    int c = n0 + base + q;
                    if (c < g.N) {
                        float vv = __uint_as_float(regs[q]);
                        if (fin && g.bias) vv += g.bias[c];
                        Cz[(size_t)r * g.N + c] = vv;
                        if (g.amax && (vv > bestv || (vv == bestv && c < besti))) {
                            bestv = vv; besti = c;
                        }
                    }
                }
            }
        }
        if (g.amax && r < g.M)
            atomicMax(&g_amax[r], amax_key(bestv, besti));
    }
    __syncthreads();
    if (wid == 0)
        asm volatile("tcgen05.dealloc.cta_group::1.sync.aligned.b32 %0, %1;"
                     :: "r"(tmem), "r"(128u));
#else
    (void)g0; (void)g1; (void)ua;   // compile-only stub (runtime picks sm_103a cubin)
#endif
}

// ---------------- elementwise / fused kernels (wait-at-top PDL) ----------
__global__ void embed_split_k(const float* __restrict__ table, const int* __restrict__ idx,
                              __nv_bfloat16* __restrict__ Ab)
{
    GDC_LAUNCH();
    GDC_WAIT();
    int i = blockIdx.x * blockDim.x + threadIdx.x;
    if (i >= S_LEN * BB * EMBD) return;
    int r = i / EMBD, e = i - r * EMBD;
    wsplit3_t(Ab, NW_EX, r, e, table[(size_t)idx[r] * EMBD + e]);
}

__global__ void gru_gate2_k(const float* __restrict__ gxf, const float* __restrict__ gxb,
                            const float* __restrict__ pf, const float* __restrict__ pb,
                            const float* __restrict__ bhf, const float* __restrict__ bhb,
                            float* __restrict__ hf, float* __restrict__ hb,
                            __nv_bfloat16* __restrict__ Ahf,
                            __nv_bfloat16* __restrict__ Ahb,
                            float* __restrict__ enc,
                            __nv_bfloat16* __restrict__ Aenc,
                            int sf, int sb)
{
    GDC_LAUNCH();
    GDC_WAIT();
    int i = blockIdx.x * blockDim.x + threadIdx.x;
    if (i >= 2 * BB * HIDN) return;
    int dir = (i >= BB * HIDN);
    int ii = dir ? i - BB * HIDN : i;
    int b = ii / HIDN, j = ii - b * HIDN;
    const float* gx = (dir ? gxb : gxf) + (size_t)b * G3;
    const float* phh = dir ? pb : pf;
    const float* bh = dir ? bhb : bhf;
    float* h = dir ? hb : hf;

    float xr = gx[j], xz = gx[HIDN + j], xn = gx[2 * HIDN + j];
    float hr = bh[j], hz = bh[HIDN + j], hn = bh[2 * HIDN + j];
    for (int z = 0; z < 4; z++) {
        const float* q = phh + ((size_t)z * BB + b) * G3;
        hr += q[j]; hz += q[HIDN + j]; hn += q[2 * HIDN + j];
    }
    float r  = 1.f / (1.f + expf(-(xr + hr)));
    float zz = 1.f / (1.f + expf(-(xz + hz)));
    float n  = tanhf(xn + r * hn);
    float h2 = (1.f - zz) * n + zz * h[ii];
    h[ii] = h2;
    wsplit3_t(dir ? Ahb : Ahf, NW_WH, b, j, h2);
    int row = (dir ? sb : sf) * BB + b;
    int col = dir ? HIDN + j : j;
    enc[(size_t)row * E2 + col] = h2;
    wsplit3_t(Aenc, NW_EN, row, col, h2);
}

__global__ void finalize_tanh_hd_k(const float* __restrict__ parts,
                                   const float* __restrict__ bias,
                                   float* __restrict__ hd,
                                   __nv_bfloat16* __restrict__ Ahd)
{
    GDC_LAUNCH();
    GDC_WAIT();
    int i = blockIdx.x * blockDim.x + threadIdx.x;
    if (i >= BB * HIDN) return;
    int b = i / HIDN, j = i - b * HIDN;
    float v = 0.f;
    for (int z = 0; z < 8; z++) v += parts[(size_t)z * BB * HIDN + i];
    v = tanhf(v + bias[j]);
    hd[i] = v;
    wsplit3_t(Ahd, NW_WH, b, j, v);
}

// fused attention: token from trg (t==0) or fused argmax of previous step
__global__ void attention_k(const float* __restrict__ pa,
                            const float* __restrict__ ep,
                            const float* __restrict__ ab,
                            const float* __restrict__ av,
                            const float* __restrict__ enc,
                            const float* __restrict__ demb,
                            const int*   __restrict__ trg, int t,
                            __nv_bfloat16* __restrict__ Ax,
                            __nv_bfloat16* __restrict__ Ami)
{
    GDC_LAUNCH();
    GDC_WAIT();
    const int b = blockIdx.x;
    const int tid = threadIdx.x;
    const int wid = tid >> 5, lane = tid & 31;
    __shared__ float hqs[ATTD];
    __shared__ float al[S_LEN];

    for (int a = tid; a < ATTD; a += 256) {
        float s = 0.f;
#pragma unroll
        for (int z = 0; z < 8; z++) s += pa[((size_t)z * BB + b) * ATTD + a];
        hqs[a] = s;
    }
    __syncthreads();

    for (int s = wid; s < S_LEN; s += 8) {
        const float* eprow = ep + ((size_t)s * BB + b) * ATTD;
        float e = 0.f;
        for (int a = lane; a < ATTD; a += 32)
            e += av[a] * tanhf(hqs[a] + eprow[a] + ab[a]);
#pragma unroll
        for (int o = 16; o; o >>= 1) e += __shfl_down_sync(0xffffffffu, e, o);
        if (lane == 0) al[s] = e;
    }
    __syncthreads();

    if (tid == 0) {
        float m = -1e30f;
        for (int s = 0; s < S_LEN; s++) m = fmaxf(m, al[s]);
        float sum = 0.f;
        for (int s = 0; s < S_LEN; s++) { float e = expf(al[s] - m); al[s] = e; sum += e; }
        float inv = 1.f / sum;
        for (int s = 0; s < S_LEN; s++) al[s] *= inv;
    }
    __syncthreads();

    for (int hc = tid; hc < E2; hc += 256) {
        float c = 0.f;
        for (int s = 0; s < S_LEN; s++)
            c += al[s] * enc[((size_t)s * BB + b) * E2 + hc];
        wsplit3_t(Ax, NW_X, b, EMBD + hc, c);
        wsplit3_t(Ami, NW_MI, b, HIDN + hc, c);
    }
    const int tok = (t == 0) ? trg[b]
                  : (int)(OUTV - (unsigned)(g_amax[b] & 0xffffffffu));
    for (int e = tid; e < EMBD; e += 256) {
        float vv = demb[(size_t)tok * EMBD + e];
        wsplit3_t(Ax, NW_X, b, e, vv);
        wsplit3_t(Ami, NW_MI, b, G3 + e, vv);
    }
}

__global__ void gru_gate_k(const float* __restrict__ gx, const float* __restrict__ bx,
                           const float* __restrict__ gh, const float* __restrict__ bh,
                           float* __restrict__ h,
                           __nv_bfloat16* __restrict__ Ahd,
                           __nv_bfloat16* __restrict__ Ami)
{
    GDC_LAUNCH();
    GDC_WAIT();
    int i = blockIdx.x * blockDim.x + threadIdx.x;
    if (i >= BB * HIDN) return;
    int b = i / HIDN, j = i - b * HIDN;
    float xr = bx[j], xz = bx[HIDN + j], xn = bx[2 * HIDN + j];
    float hr = bh[j], hz = bh[HIDN + j], hn = bh[2 * HIDN + j];
    for (int z = 0; z < 4; z++) {
        const float* q1 = gx + ((size_t)z * BB + b) * G3;
        const float* q2 = gh + ((size_t)z * BB + b) * G3;
        xr += q1[j]; xz += q1[HIDN + j]; xn += q1[2 * HIDN + j];
        hr += q2[j]; hz += q2[HIDN + j]; hn += q2[2 * HIDN + j];
    }
    float r  = 1.f / (1.f + expf(-(xr + hr)));
    float zz = 1.f / (1.f + expf(-(xz + hz)));
    float n  = tanhf(xn + r * hn);
    float h2 = (1.f - zz) * n + zz * h[i];
    h[i] = h2;
    wsplit3_t(Ahd, NW_WH, b, j, h2);
    wsplit3_t(Ami, NW_MI, b, j, h2);
}

// maxout finalize + zero the argmax accumulator for this step's vocab GEMM
__global__ void finalize_max_k(const float* __restrict__ pm,
                               const float* __restrict__ bias,
                               __nv_bfloat16* __restrict__ Atm)
{
    GDC_LAUNCH();
    GDC_WAIT();
    int i = blockIdx.x * blockDim.x + threadIdx.x;
    if (i < BB) g_amax[i] = 0ull;
    if (i >= BB * MXO) return;
    int b = i / MXO, o = i - b * MXO;
    float v0 = bias[2 * o], v1 = bias[2 * o + 1];
    for (int z = 0; z < 8; z++) {
        const float* q = pm + ((size_t)z * BB + b) * MX2;
        v0 += q[2 * o]; v1 += q[2 * o + 1];
    }
    wsplit3_t(Atm, NW_TM, b, o, fmaxf(v0, v1));
}

// ---------------- host ----------------
static inline int up(int n, int b) { return (n + b - 1) / b; }

static inline TG mkt(const __nv_bfloat16* Ab, const __nv_bfloat16* Wb,
                     const float* bias, float* C, int M, int N, int nwin,
                     int split, int amax = 0)
{
    TG g; g.Ab = Ab; g.Wb = Wb; g.bias = bias; g.C = C;
    g.M = M; g.N = N; g.nwin = nwin; g.split = split; g.amax = amax;
    return g;
}
static inline int units(const TG& g)
{
    return ((g.M + 127) >> 7) * ((g.N + 127) >> 7) * g.split;
}

template <typename F, typename... Args>
static inline void pdl(F f, int grid, int block, size_t smem, Args... args)
{
    cudaLaunchConfig_t cfg = {};
    cfg.gridDim = dim3((unsigned)grid);
    cfg.blockDim = dim3((unsigned)block);
    cfg.dynamicSmemBytes = smem;
    cfg.stream = 0;
    cudaLaunchAttribute at;
    at.id = cudaLaunchAttributeProgrammaticStreamSerialization;
    at.val.programmaticStreamSerializationAllowed = 1;
    cfg.attrs = &at;
    cfg.numAttrs = 1;
    cudaLaunchKernelEx(&cfg, f, args...);
}

static inline void tg1(const TG& g)
{
    pdl(tgemm_k, units(g), 128, (size_t)TG_SMEM, g, g, units(g));
}
static inline void tg2(const TG& a, const TG& b)
{
    pdl(tgemm_k, units(a) + units(b), 128, (size_t)TG_SMEM, a, b, units(a));
}
static inline void wconv(const float* W, int rs, int co,
                         __nv_bfloat16* Wb, int N, int K, int nwin)
{
    int NT = (N + 127) >> 7;
    size_t tot = (size_t)NT * 128 * nwin * 64;
    pdl(wconv_k, (int)((tot + 255) / 256), 256, (size_t)0, W, rs, co, Wb, N, K, nwin);
}

extern "C" void kernel_launch(void* const* d_in, const int* in_sizes, int n_in,
                              void* d_out, int out_size)
{
    (void)in_sizes; (void)n_in; (void)out_size;
    const int*   src      = (const int*)  d_in[0];
    const int*   trg      = (const int*)  d_in[1];
    const float* enc_emb  = (const float*)d_in[2];
    const float* enc_wx_f = (const float*)d_in[3];
    const float* enc_wh_f = (const float*)d_in[4];
    const float* enc_bx_f = (const float*)d_in[5];
    const float* enc_bh_f = (const float*)d_in[6];
    const float* enc_wx_b = (const float*)d_in[7];
    const float* enc_wh_b = (const float*)d_in[8];
    const float* enc_bx_b = (const float*)d_in[9];
    const float* enc_bh_b = (const float*)d_in[10];
    const float* enc_fc_w = (const float*)d_in[11];
    const float* enc_fc_b = (const float*)d_in[12];
    const float* attn_w   = (const float*)d_in[13];
    const float* attn_b   = (const float*)d_in[14];
    const float* attn_v   = (const float*)d_in[15];
    const float* dec_emb  = (const float*)d_in[16];
    const float* dec_wx   = (const float*)d_in[17];
    const float* dec_wh   = (const float*)d_in[18];
    const float* dec_bx   = (const float*)d_in[19];
    const float* dec_bh   = (const float*)d_in[20];
    const float* max_w    = (const float*)d_in[21];
    const float* max_b    = (const float*)d_in[22];
    const float* out_w    = (const float*)d_in[23];
    const float* out_b    = (const float*)d_in[24];

    cudaFuncSetAttribute(tgemm_k, cudaFuncAttributeMaxDynamicSharedMemorySize, TG_SMEM);

    float* ws = nullptr;
    __nv_bfloat16* wb = nullptr; __nv_bfloat16* abx = nullptr;
    cudaGetSymbolAddress((void**)&ws, g_ws);
    cudaGetSymbolAddress((void**)&wb, g_wb);
    cudaGetSymbolAddress((void**)&abx, g_ab);

    float* gxf = ws + O_GXF;
    float* gxb = ws + O_GXB;
    float* enc = ws + O_ENC;
    float* ep  = ws + O_EP;
    float* pa  = ws + O_PA;
    float* pb  = ws + O_PB;
    float* pm  = ws + O_PM;
    float* hf  = ws + O_HF;
    float* hb  = ws + O_HB;
    float* hd  = ws + O_HD;
    float* out = (float*)d_out;

    __nv_bfloat16* Aemb = abx + AB_EMB;
    __nv_bfloat16* Aenc = abx + AB_ENC;
    __nv_bfloat16* Ahf  = abx + AB_HF;
    __nv_bfloat16* Ahb  = abx + AB_HB;
    __nv_bfloat16* Ahd  = abx + AB_HD;
    __nv_bfloat16* Ax   = abx + AB_X;
    __nv_bfloat16* Ami  = abx + AB_MI;
    __nv_bfloat16* Atm  = abx + AB_TM;

    // weight conversion (independent nodes; PDL overlaps them)
    wconv(enc_wx_f, EMBD, 0,    wb + WB_EXF, 3000, EMBD, NW_EX);
    wconv(enc_wx_b, EMBD, 0,    wb + WB_EXB, 3000, EMBD, NW_EX);
    wconv(enc_wh_f, HIDN, 0,    wb + WB_WHF, 3000, HIDN, NW_WH);
    wconv(enc_wh_b, HIDN, 0,    wb + WB_WHB, 3000, HIDN, NW_WH);
    wconv(enc_fc_w, HIDN, 0,    wb + WB_FC,  1000, HIDN, NW_WH);
    wconv(attn_w,   G3,   0,    wb + WB_AWH, 1000, HIDN, NW_WH);
    wconv(attn_w,   G3,   HIDN, wb + WB_AWE, 1000, E2,   NW_EN);
    wconv(dec_wx,   DXK,  0,    wb + WB_DWX, 3000, DXK,  NW_X);
    wconv(dec_wh,   HIDN, 0,    wb + WB_DWH, 3000, HIDN, NW_WH);
    wconv(max_w,    MXK,  0,    wb + WB_MXW, 1000, MXK,  NW_MI);
    wconv(out_w,    MXO,  0,    wb + WB_OUW, 30000, MXO, NW_TM);

    // non-PDL memset nodes: hard barrier stopping the PDL cascade here
    cudaMemsetAsync(abx, 0, AB_TOT * sizeof(__nv_bfloat16));
    cudaMemsetAsync(hf, 0, (size_t)2 * BB * HIDN * sizeof(float));  // hf+hb adjacent
    cudaMemsetAsync(out, 0, (size_t)BB * OUTV * sizeof(float));

    // ---------------- Encoder ----------------
    pdl(embed_split_k, up(S_LEN * BB * EMBD, 256), 256, (size_t)0, enc_emb, src, Aemb);
    tg2(mkt(Aemb, wb + WB_EXF, enc_bx_f, gxf, S_LEN * BB, G3, NW_EX, 1),
        mkt(Aemb, wb + WB_EXB, enc_bx_b, gxb, S_LEN * BB, G3, NW_EX, 1));

    for (int s = 0; s < S_LEN; s++) {
        int sb = S_LEN - 1 - s;
        tg2(mkt(Ahf, wb + WB_WHF, nullptr, pa, BB, G3, NW_WH, 4),
            mkt(Ahb, wb + WB_WHB, nullptr, pb, BB, G3, NW_WH, 4));
        pdl(gru_gate2_k, up(2 * BB * HIDN, 256), 256, (size_t)0,
            gxf + (size_t)s * BB * G3, gxb + (size_t)sb * BB * G3,
            pa, pb, enc_bh_f, enc_bh_b, hf, hb, Ahf, Ahb, enc, Aenc, s, sb);
    }

    tg1(mkt(Ahb, wb + WB_FC, nullptr, pa, BB, HIDN, NW_WH, 8));
    pdl(finalize_tanh_hd_k, up(BB * HIDN, 256), 256, (size_t)0, pa, enc_fc_b, hd, Ahd);
    // e_part + initial hq (dual)
    tg2(mkt(Aenc, wb + WB_AWE, nullptr, ep, S_LEN * BB, ATTD, NW_EN, 1),
        mkt(Ahd, wb + WB_AWH, nullptr, pa, BB, ATTD, NW_WH, 8));

    // ---------------- Decoder ----------------
    for (int t = 0; t < T_LEN - 1; t++) {
        pdl(attention_k, BB, 256, (size_t)0,
            pa, ep, attn_b, attn_v, enc, dec_emb, trg, t, Ax, Ami);
        tg2(mkt(Ax,  wb + WB_DWX, nullptr, pa, BB, G3, NW_X,  4),
            mkt(Ahd, wb + WB_DWH, nullptr, pb, BB, G3, NW_WH, 4));
        pdl(gru_gate_k, up(BB * HIDN, 256), 256, (size_t)0,
            pa, dec_bx, pb, dec_bh, hd, Ahd, Ami);
        // maxout GEMM + next-step hq GEMM (dual); hq writes pa (free after gate)
        tg2(mkt(Ami, wb + WB_MXW, nullptr, pm, BB, MX2, NW_MI, 8),
            mkt(Ahd, wb + WB_AWH, nullptr, pa, BB, ATTD, NW_WH, 8));
        pdl(finalize_max_k, up(BB * MXO, 256), 256, (size_t)0, pm, max_b, Atm);
        float* pred = out + (size_t)(t + 1) * BB * OUTV;
        tg1(mkt(Atm, wb + WB_OUW, out_b, pred, BB, OUTV, NW_TM, 1, 1));
    }
}

// round 15
// speedup vs baseline: 1.1039x; 1.0809x over previous
#include <cuda_runtime.h>
#include <cuda_bf16.h>
#include <math.h>
#include <stdint.h>

#define S_LEN 40
#define T_LEN 30
#define BB    64
#define EMBD  620
#define HIDN  1000
#define ATTD  1000
#define MXO   500
#define OUTV  30000
#define G3    3000
#define E2    2000
#define DXK   2620
#define MXK   3620
#define MX2   1000

// windows (64 K-cols each) per operand family
#define NW_EX  10
#define NW_WH  16
#define NW_EN  32
#define NW_X   41
#define NW_MI  57
#define NW_TM  8

#define TILE_E 8192
#define TILE_B 16384

// ---------------- fp32 workspace ----------------
static const size_t O_GXF = 0;
static const size_t O_GXB = O_GXF + (size_t)S_LEN*BB*G3;
static const size_t O_ENC = O_GXB + (size_t)S_LEN*BB*G3;
static const size_t O_EP  = O_ENC + (size_t)S_LEN*BB*E2;
static const size_t O_PA  = O_EP  + (size_t)S_LEN*BB*ATTD;
static const size_t O_PB  = O_PA  + (size_t)8*BB*G3;
static const size_t O_PM  = O_PB  + (size_t)8*BB*G3;
static const size_t O_HF  = O_PM  + (size_t)16*BB*MX2;
static const size_t O_HB  = O_HF  + (size_t)BB*HIDN;
static const size_t O_HD  = O_HB  + (size_t)BB*HIDN;
static const size_t ARENA = O_HD  + (size_t)BB*HIDN;

__device__ __align__(256) float g_ws[ARENA];
__device__ unsigned long long g_amax[BB];

// ---------------- tiled bf16 weight arena (tile = 16KB smem image) --------
static const size_t WB_EXF = 0;
static const size_t WB_EXB = WB_EXF + (size_t)24*NW_EX*3*TILE_E;
static const size_t WB_WHF = WB_EXB + (size_t)24*NW_EX*3*TILE_E;
static const size_t WB_WHB = WB_WHF + (size_t)24*NW_WH*3*TILE_E;
static const size_t WB_FC  = WB_WHB + (size_t)24*NW_WH*3*TILE_E;
static const size_t WB_AWH = WB_FC  + (size_t)8*NW_WH*3*TILE_E;
static const size_t WB_AWE = WB_AWH + (size_t)8*NW_WH*3*TILE_E;
static const size_t WB_DWX = WB_AWE + (size_t)8*NW_EN*3*TILE_E;
static const size_t WB_DWH = WB_DWX + (size_t)24*NW_X*3*TILE_E;
static const size_t WB_MXW = WB_DWH + (size_t)24*NW_WH*3*TILE_E;
static const size_t WB_OUW = WB_MXW + (size_t)8*NW_MI*3*TILE_E;
static const size_t WB_TOT = WB_OUW + (size_t)235*NW_TM*3*TILE_E;

__device__ __align__(256) __nv_bfloat16 g_wb[WB_TOT];

// ---------------- tiled bf16 activation arena ----------------
static const size_t AB_EMB = 0;
static const size_t AB_ENC = AB_EMB + (size_t)20*NW_EX*3*TILE_E;
static const size_t AB_HF  = AB_ENC + (size_t)20*NW_EN*3*TILE_E;
static const size_t AB_HB  = AB_HF  + (size_t)NW_WH*3*TILE_E;
static const size_t AB_HD  = AB_HB  + (size_t)NW_WH*3*TILE_E;
static const size_t AB_X   = AB_HD  + (size_t)NW_WH*3*TILE_E;
static const size_t AB_MI  = AB_X   + (size_t)NW_X*3*TILE_E;
static const size_t AB_TM  = AB_MI  + (size_t)NW_MI*3*TILE_E;
static const size_t AB_TOT = AB_TM  + (size_t)NW_TM*3*TILE_E;

__device__ __align__(256) __nv_bfloat16 g_ab[AB_TOT];

// ---------------- helpers ----------------
__device__ __forceinline__ uint32_t su32(const void* p)
{
    uint32_t a;
    asm("{ .reg .u64 t; cvta.to.shared.u64 t, %1; cvt.u32.u64 %0, t; }"
        : "=r"(a) : "l"(p));
    return a;
}
__device__ __forceinline__ uint64_t mkdesc(uint32_t addr)
{
    const uint64_t base = (uint64_t(2) << 61) | (uint64_t(1) << 46) |
                          (uint64_t(64) << 32) | (uint64_t(1) << 16);
    return base | ((uint64_t)(addr >> 4) & 0x3FFF);
}
__device__ __forceinline__ void mbar_init(uint32_t mb, uint32_t cnt)
{
    asm volatile("mbarrier.init.shared.b64 [%0], %1;" :: "r"(mb), "r"(cnt) : "memory");
}
__device__ __forceinline__ void mbar_wait(uint32_t mb, int parity)
{
    asm volatile(
        "{\n\t.reg .pred P;\n\t"
        "WL_%=:\n\t"
        "mbarrier.try_wait.parity.acquire.cta.shared::cta.b64 P, [%0], %1, 0x989680;\n\t"
        "@P bra.uni WD_%=;\n\t"
        "bra.uni WL_%=;\n\t"
        "WD_%=:\n\t}"
        :: "r"(mb), "r"(parity) : "memory");
}
__device__ __forceinline__ void expect_tx(uint32_t mb, uint32_t bytes)
{
    asm volatile("mbarrier.arrive.expect_tx.shared.b64 _, [%0], %1;"
                 :: "r"(mb), "r"(bytes) : "memory");
}
__device__ __forceinline__ void bulk_g2s(uint32_t dst, const void* src, uint32_t mb)
{
    asm volatile(
        "cp.async.bulk.shared::cluster.global.mbarrier::complete_tx::bytes [%0], [%1], %2, [%3];"
        :: "r"(dst), "l"(src), "r"((uint32_t)TILE_B), "r"(mb) : "memory");
}
__device__ __forceinline__ void mma_bf16_ss(uint32_t d, uint64_t ad, uint64_t bd,
                                            uint32_t idesc, uint32_t acc)
{
    asm volatile(
        "{\n\t.reg .pred p;\n\t"
        "setp.ne.u32 p, %5, 0;\n\t"
        "tcgen05.mma.cta_group::1.kind::f16 [%0], %1, %2, %3, {%4,%4,%4,%4}, p;\n\t}"
        :: "r"(d), "l"(ad), "l"(bd), "r"(idesc), "r"(0u), "r"(acc) : "memory");
}
__device__ __forceinline__ void tc_commit(uint32_t mb)
{
    asm volatile(
        "tcgen05.commit.cta_group::1.mbarrier::arrive::one.shared::cluster.b64 [%0];"
        :: "r"(mb) : "memory");
}
#define LDTM_X32(r, ta) \
    asm volatile( \
        "tcgen05.ld.sync.aligned.32x32b.x32.b32 " \
        "{%0,%1,%2,%3,%4,%5,%6,%7,%8,%9,%10,%11,%12,%13,%14,%15," \
        "%16,%17,%18,%19,%20,%21,%22,%23,%24,%25,%26,%27,%28,%29,%30,%31}, [%32];" \
        : "=r"((r)[0]),"=r"((r)[1]),"=r"((r)[2]),"=r"((r)[3]), \
          "=r"((r)[4]),"=r"((r)[5]),"=r"((r)[6]),"=r"((r)[7]), \
          "=r"((r)[8]),"=r"((r)[9]),"=r"((r)[10]),"=r"((r)[11]), \
          "=r"((r)[12]),"=r"((r)[13]),"=r"((r)[14]),"=r"((r)[15]), \
          "=r"((r)[16]),"=r"((r)[17]),"=r"((r)[18]),"=r"((r)[19]), \
          "=r"((r)[20]),"=r"((r)[21]),"=r"((r)[22]),"=r"((r)[23]), \
          "=r"((r)[24]),"=r"((r)[25]),"=r"((r)[26]),"=r"((r)[27]), \
          "=r"((r)[28]),"=r"((r)[29]),"=r"((r)[30]),"=r"((r)[31]) \
        : "r"(ta))

#define TG_IDESC 0x8200490u
// single-buffered: 6 tiles -> 97KB => 2 CTAs/SM co-resident
#define TG_SMEM  (1024 + 6 * TILE_B)

__device__ __forceinline__ size_t toff(int nwin, int R, int k)
{
    uint32_t inner = (uint32_t)((R & 127) * 128 + (k & 63) * 2);
    inner ^= (inner >> 3) & 0x70;
    return ((size_t)(((R >> 7) * nwin + (k >> 6)) * 3) << 13) + (inner >> 1);
}
__device__ __forceinline__ void wsplit3_t(__nv_bfloat16* base, int nwin, int R, int k, float a)
{
    __nv_bfloat16 h = __float2bfloat16(a);
    float r1 = a - __bfloat162float(h);
    __nv_bfloat16 m = __float2bfloat16(r1);
    float r2 = r1 - __bfloat162float(m);
    size_t o = toff(nwin, R, k);
    base[o] = h;
    base[o + TILE_E] = m;
    base[o + 2 * TILE_E] = __float2bfloat16(r2);
}
__device__ __forceinline__ unsigned long long amax_key(float v, int idx)
{
    unsigned u = __float_as_uint(v);
    u = (u & 0x80000000u) ? ~u : (u | 0x80000000u);
    return ((unsigned long long)u << 32) | (unsigned)(OUTV - idx);
}

// ---------------- batched weight conversion: all 11 jobs, one node --------
#define NWJ 11
struct WJobs {
    const float* W[NWJ];
    long long    off[NWJ];       // bf16 offset into g_wb
    int rs[NWJ], co[NWJ], N[NWJ], K[NWJ], nwin[NWJ];
    int b0[NWJ + 1];             // block-range prefix
};

__global__ void wconv_mega_k(WJobs jb, __nv_bfloat16* __restrict__ base)
{
    const int blk = blockIdx.x;
    int j = 0;
    while (j < NWJ - 1 && blk >= jb.b0[j + 1]) j++;
    const int nwin = jb.nwin[j];
    const int Kp = nwin * 64;
    const int NT = (jb.N[j] + 127) >> 7;
    const size_t tot = (size_t)NT * 128 * Kp;
    size_t i = (size_t)(blk - jb.b0[j]) * 256 + threadIdx.x;
    if (i >= tot) return;
    int R = (int)(i / Kp), k = (int)(i - (size_t)R * Kp);
    float a = (R < jb.N[j] && k < jb.K[j])
            ? jb.W[j][(size_t)R * jb.rs[j] + jb.co[j] + k] : 0.f;
    wsplit3_t(base + jb.off[j], nwin, R, k, a);
}

// ---------------------------------------------------------------------------
// tcgen05 GEMM, TMA-bulk staged, single-buffered (2 CTAs/SM overlap).
// One CTA = one (tile, split) unit. Grid.x = units(g0)+units(g1).
// amax=1: fused per-row argmax via atomicMax into g_amax (final-split only).
// ---------------------------------------------------------------------------
struct TG {
    const __nv_bfloat16* Ab;
    const __nv_bfloat16* Wb;
    const float* bias;
    float* C;
    int M, N, nwin, split, amax;
};

__global__ void __launch_bounds__(128) tgemm_k(TG g0, TG g1, int ua)
{
#if defined(__CUDA_ARCH_FEAT_SM103_ALL)
    const int u = blockIdx.x;
    const TG g = (u < ua) ? g0 : g1;
    int v = (u < ua) ? u : u - ua;
    const int ntn = (g.N + 127) >> 7;
    const int z = v % g.split;
    const int rest = v / g.split;
    const int nt = rest % ntn;
    const int mt = rest / ntn;
    const int nwin = g.nwin;
    const int kcw = (nwin + g.split - 1) / g.split;
    const int w0 = z * kcw;
    int w1 = w0 + kcw; if (w1 > nwin) w1 = nwin;
    const int nw = (w1 > w0) ? (w1 - w0) : 0;
    const int m0 = mt << 7, n0 = nt << 7;
    const bool fin = (g.split == 1);
    float* Cz = g.C + (size_t)z * g.M * g.N;

    const int tid = threadIdx.x;
    const int wid = tid >> 5, lane = tid & 31;

    extern __shared__ __align__(16) char dyn[];
    const uint32_t dbase = (su32(dyn) + 1023u) & ~1023u;

    __shared__ __align__(8) unsigned long long s_bar[2];  // ld, mm
    __shared__ uint32_t s_tptr;

    if (wid == 0) {
        asm volatile("tcgen05.alloc.cta_group::1.sync.aligned.shared::cta.b32 [%0], %1;"
                     :: "r"(su32(&s_tptr)), "r"(128u) : "memory");
        asm volatile("tcgen05.relinquish_alloc_permit.cta_group::1.sync.aligned;");
    }
    if (tid == 0) { mbar_init(su32(&s_bar[0]), 1); mbar_init(su32(&s_bar[1]), 1); }
    __syncthreads();
    const uint32_t tmem = s_tptr;

    if (nw > 0 && tid == 0) {
        const uint32_t ld = su32(&s_bar[0]);
        const uint32_t mm = su32(&s_bar[1]);
        int pl = 0, pq = 0;
        const char* At = (const char*)g.Ab;
        const char* Bt = (const char*)g.Wb;
        const int segA[6] = {0, 1, 2, 0, 1, 0};
        const int segB[6] = {0, 0, 0, 1, 1, 2};
        bool first = true;

        for (int i = 0; i < nw; i++) {
            const int w = w0 + i;
            expect_tx(ld, 6u * TILE_B);
            const size_t abase = ((size_t)((mt * nwin + w) * 3)) * TILE_B;
            const size_t bbase = ((size_t)((nt * nwin + w) * 3)) * TILE_B;
#pragma unroll
            for (int p = 0; p < 3; p++) {
                bulk_g2s(dbase + (uint32_t)p * TILE_B, At + abase + (size_t)p * TILE_B, ld);
                bulk_g2s(dbase + (uint32_t)(3 + p) * TILE_B, Bt + bbase + (size_t)p * TILE_B, ld);
            }
            mbar_wait(ld, pl); pl ^= 1;
#pragma unroll
            for (int s = 0; s < 6; s++) {
                uint64_t ad = mkdesc(dbase + (uint32_t)segA[s] * TILE_B);
                uint64_t bd = mkdesc(dbase + (uint32_t)(3 + segB[s]) * TILE_B);
#pragma unroll
                for (int q = 0; q < 4; q++) {
                    mma_bf16_ss(tmem, ad + 2 * q, bd + 2 * q, TG_IDESC, first ? 0u : 1u);
                    first = false;
                }
            }
            tc_commit(mm);
            mbar_wait(mm, pq); pq ^= 1;   // single buffer: drain before reuse
        }
    }
    __syncthreads();
    asm volatile("tcgen05.fence::after_thread_sync;" ::: "memory");

    // epilogue
    const int r = m0 + wid * 32 + lane;
    if (nw == 0) {
        if (r < g.M)
            for (int c0 = 0; c0 < 128; c0++) {
                int c = n0 + c0;
                if (c < g.N) Cz[(size_t)r * g.N + c] = (fin && g.bias) ? g.bias[c] : 0.f;
            }
    } else {
        float bestv = -1e30f; int besti = 0;
#pragma unroll
        for (int base = 0; base < 128; base += 32) {
            uint32_t regs[32];
            LDTM_X32(regs, tmem + base);
            asm volatile("tcgen05.wait::ld.sync.aligned;" ::: "memory");
            if (r < g.M) {
#pragma unroll
                for (int q = 0; q < 32; q++) {
                    int c = n0 + base + q;
                    if (c < g.N) {
                        float vv = __uint_as_float(regs[q]);
                        if (fin && g.bias) vv += g.bias[c];
                        Cz[(size_t)r * g.N + c] = vv;
                        if (g.amax && (vv > bestv || (vv == bestv && c < besti))) {
                            bestv = vv; besti = c;
                        }
                    }
                }
            }
        }
        if (g.amax && r < g.M)
            atomicMax(&g_amax[r], amax_key(bestv, besti));
    }
    __syncthreads();
    if (wid == 0)
        asm volatile("tcgen05.dealloc.cta_group::1.sync.aligned.b32 %0, %1;"
                     :: "r"(tmem), "r"(128u));
#else
    (void)g0; (void)g1; (void)ua;   // compile-only stub (runtime picks sm_103a cubin)
#endif
}

// ---------------- elementwise / fused kernels ----------------
__global__ void embed_split_k(const float* __restrict__ table, const int* __restrict__ idx,
                              __nv_bfloat16* __restrict__ Ab)
{
    int i = blockIdx.x * blockDim.x + threadIdx.x;
    if (i >= S_LEN * BB * EMBD) return;
    int r = i / EMBD, e = i - r * EMBD;
    wsplit3_t(Ab, NW_EX, r, e, table[(size_t)idx[r] * EMBD + e]);
}

__global__ void gru_gate2_k(const float* __restrict__ gxf, const float* __restrict__ gxb,
                            const float* __restrict__ pf, const float* __restrict__ pb,
                            const float* __restrict__ bhf, const float* __restrict__ bhb,
                            float* __restrict__ hf, float* __restrict__ hb,
                            __nv_bfloat16* __restrict__ Ahf,
                            __nv_bfloat16* __restrict__ Ahb,
                            float* __restrict__ enc,
                            __nv_bfloat16* __restrict__ Aenc,
                            int sf, int sb)
{
    int i = blockIdx.x * blockDim.x + threadIdx.x;
    if (i >= 2 * BB * HIDN) return;
    int dir = (i >= BB * HIDN);
    int ii = dir ? i - BB * HIDN : i;
    int b = ii / HIDN, j = ii - b * HIDN;
    const float* gx = (dir ? gxb : gxf) + (size_t)b * G3;
    const float* phh = dir ? pb : pf;
    const float* bh = dir ? bhb : bhf;
    float* h = dir ? hb : hf;

    float xr = gx[j], xz = gx[HIDN + j], xn = gx[2 * HIDN + j];
    float hr = bh[j], hz = bh[HIDN + j], hn = bh[2 * HIDN + j];
    for (int z = 0; z < 4; z++) {
        const float* q = phh + ((size_t)z * BB + b) * G3;
        hr += q[j]; hz += q[HIDN + j]; hn += q[2 * HIDN + j];
    }
    float r  = 1.f / (1.f + expf(-(xr + hr)));
    float zz = 1.f / (1.f + expf(-(xz + hz)));
    float n  = tanhf(xn + r * hn);
    float h2 = (1.f - zz) * n + zz * h[ii];
    h[ii] = h2;
    wsplit3_t(dir ? Ahb : Ahf, NW_WH, b, j, h2);
    int row = (dir ? sb : sf) * BB + b;
    int col = dir ? HIDN + j : j;
    enc[(size_t)row * E2 + col] = h2;
    wsplit3_t(Aenc, NW_EN, row, col, h2);
}

__global__ void finalize_tanh_hd_k(const float* __restrict__ parts,
                                   const float* __restrict__ bias,
                                   float* __restrict__ hd,
                                   __nv_bfloat16* __restrict__ Ahd)
{
    int i = blockIdx.x * blockDim.x + threadIdx.x;
    if (i >= BB * HIDN) return;
    int b = i / HIDN, j = i - b * HIDN;
    float v = 0.f;
    for (int z = 0; z < 8; z++) v += parts[(size_t)z * BB * HIDN + i];
    v = tanhf(v + bias[j]);
    hd[i] = v;
    wsplit3_t(Ahd, NW_WH, b, j, v);
}

// fused attention: token from trg (t==0) or fused argmax of previous step
__global__ void attention_k(const float* __restrict__ pa,
                            const float* __restrict__ ep,
                            const float* __restrict__ ab,
                            const float* __restrict__ av,
                            const float* __restrict__ enc,
                            const float* __restrict__ demb,
                            const int*   __restrict__ trg, int t,
                            __nv_bfloat16* __restrict__ Ax,
                            __nv_bfloat16* __restrict__ Ami)
{
    const int b = blockIdx.x;
    const int tid = threadIdx.x;
    const int wid = tid >> 5, lane = tid & 31;
    __shared__ float hqs[ATTD];
    __shared__ float al[S_LEN];

    for (int a = tid; a < ATTD; a += 256) {
        float s = 0.f;
#pragma unroll
        for (int z = 0; z < 8; z++) s += pa[((size_t)z * BB + b) * ATTD + a];
        hqs[a] = s;
    }
    __syncthreads();

    for (int s = wid; s < S_LEN; s += 8) {
        const float* eprow = ep + ((size_t)s * BB + b) * ATTD;
        float e = 0.f;
        for (int a = lane; a < ATTD; a += 32)
            e += av[a] * tanhf(hqs[a] + eprow[a] + ab[a]);
#pragma unroll
        for (int o = 16; o; o >>= 1) e += __shfl_down_sync(0xffffffffu, e, o);
        if (lane == 0) al[s] = e;
    }
    __syncthreads();

    if (tid == 0) {
        float m = -1e30f;
        for (int s = 0; s < S_LEN; s++) m = fmaxf(m, al[s]);
        float sum = 0.f;
        for (int s = 0; s < S_LEN; s++) { float e = expf(al[s] - m); al[s] = e; sum += e; }
        float inv = 1.f / sum;
        for (int s = 0; s < S_LEN; s++) al[s] *= inv;
    }
    __syncthreads();

    for (int hc = tid; hc < E2; hc += 256) {
        float c = 0.f;
        for (int s = 0; s < S_LEN; s++)
            c += al[s] * enc[((size_t)s * BB + b) * E2 + hc];
        wsplit3_t(Ax, NW_X, b, EMBD + hc, c);
        wsplit3_t(Ami, NW_MI, b, HIDN + hc, c);
    }
    const int tok = (t == 0) ? trg[b]
                  : (int)(OUTV - (unsigned)(g_amax[b] & 0xffffffffu));
    for (int e = tid; e < EMBD; e += 256) {
        float vv = demb[(size_t)tok * EMBD + e];
        wsplit3_t(Ax, NW_X, b, e, vv);
        wsplit3_t(Ami, NW_MI, b, G3 + e, vv);
    }
}

// decoder GRU gate (8 partials per operand with split 8)
__global__ void gru_gate_k(const float* __restrict__ gx, const float* __restrict__ bx,
                           const float* __restrict__ gh, const float* __restrict__ bh,
                           float* __restrict__ h,
                           __nv_bfloat16* __restrict__ Ahd,
                           __nv_bfloat16* __restrict__ Ami)
{
    int i = blockIdx.x * blockDim.x + threadIdx.x;
    if (i >= BB * HIDN) return;
    int b = i / HIDN, j = i - b * HIDN;
    float xr = bx[j], xz = bx[HIDN + j], xn = bx[2 * HIDN + j];
    float hr = bh[j], hz = bh[HIDN + j], hn = bh[2 * HIDN + j];
    for (int z = 0; z < 8; z++) {
        const float* q1 = gx + ((size_t)z * BB + b) * G3;
        const float* q2 = gh + ((size_t)z * BB + b) * G3;
        xr += q1[j]; xz += q1[HIDN + j]; xn += q1[2 * HIDN + j];
        hr += q2[j]; hz += q2[HIDN + j]; hn += q2[2 * HIDN + j];
    }
    float r  = 1.f / (1.f + expf(-(xr + hr)));
    float zz = 1.f / (1.f + expf(-(xz + hz)));
    float n  = tanhf(xn + r * hn);
    float h2 = (1.f - zz) * n + zz * h[i];
    h[i] = h2;
    wsplit3_t(Ahd, NW_WH, b, j, h2);
    wsplit3_t(Ami, NW_MI, b, j, h2);
}

// maxout finalize (16 partials) + zero argmax accumulator
__global__ void finalize_max_k(const float* __restrict__ pm,
                               const float* __restrict__ bias,
                               __nv_bfloat16* __restrict__ Atm)
{
    int i = blockIdx.x * blockDim.x + threadIdx.x;
    if (i < BB) g_amax[i] = 0ull;
    if (i >= BB * MXO) return;
    int b = i / MXO, o = i - b * MXO;
    float v0 = bias[2 * o], v1 = bias[2 * o + 1];
    for (int z = 0; z < 16; z++) {
        const float* q = pm + ((size_t)z * BB + b) * MX2;
        v0 += q[2 * o]; v1 += q[2 * o + 1];
    }
    wsplit3_t(Atm, NW_TM, b, o, fmaxf(v0, v1));
}

// ---------------- host ----------------
static inline int up(int n, int b) { return (n + b - 1) / b; }

static inline TG mkt(const __nv_bfloat16* Ab, const __nv_bfloat16* Wb,
                     const float* bias, float* C, int M, int N, int nwin,
                     int split, int amax = 0)
{
    TG g; g.Ab = Ab; g.Wb = Wb; g.bias = bias; g.C = C;
    g.M = M; g.N = N; g.nwin = nwin; g.split = split; g.amax = amax;
    return g;
}
static inline int units(const TG& g)
{
    return ((g.M + 127) >> 7) * ((g.N + 127) >> 7) * g.split;
}
static inline void tg1(const TG& g)
{
    tgemm_k<<<units(g), 128, TG_SMEM>>>(g, g, units(g));
}
static inline void tg2(const TG& a, const TG& b)
{
    tgemm_k<<<units(a) + units(b), 128, TG_SMEM>>>(a, b, units(a));
}

extern "C" void kernel_launch(void* const* d_in, const int* in_sizes, int n_in,
                              void* d_out, int out_size)
{
    (void)in_sizes; (void)n_in; (void)out_size;
    const int*   src      = (const int*)  d_in[0];
    const int*   trg      = (const int*)  d_in[1];
    const float* enc_emb  = (const float*)d_in[2];
    const float* enc_wx_f = (const float*)d_in[3];
    const float* enc_wh_f = (const float*)d_in[4];
    const float* enc_bx_f = (const float*)d_in[5];
    const float* enc_bh_f = (const float*)d_in[6];
    const float* enc_wx_b = (const float*)d_in[7];
    const float* enc_wh_b = (const float*)d_in[8];
    const float* enc_bx_b = (const float*)d_in[9];
    const float* enc_bh_b = (const float*)d_in[10];
    const float* enc_fc_w = (const float*)d_in[11];
    const float* enc_fc_b = (const float*)d_in[12];
    const float* attn_w   = (const float*)d_in[13];
    const float* attn_b   = (const float*)d_in[14];
    const float* attn_v   = (const float*)d_in[15];
    const float* dec_emb  = (const float*)d_in[16];
    const float* dec_wx   = (const float*)d_in[17];
    const float* dec_wh   = (const float*)d_in[18];
    const float* dec_bx   = (const float*)d_in[19];
    const float* dec_bh   = (const float*)d_in[20];
    const float* max_w    = (const float*)d_in[21];
    const float* max_b    = (const float*)d_in[22];
    const float* out_w    = (const float*)d_in[23];
    const float* out_b    = (const float*)d_in[24];

    cudaFuncSetAttribute(tgemm_k, cudaFuncAttributeMaxDynamicSharedMemorySize, TG_SMEM);

    float* ws = nullptr;
    __nv_bfloat16* wb = nullptr; __nv_bfloat16* abx = nullptr;
    cudaGetSymbolAddress((void**)&ws, g_ws);
    cudaGetSymbolAddress((void**)&wb, g_wb);
    cudaGetSymbolAddress((void**)&abx, g_ab);

    float* gxf = ws + O_GXF;
    float* gxb = ws + O_GXB;
    float* enc = ws + O_ENC;
    float* ep  = ws + O_EP;
    float* pa  = ws + O_PA;
    float* pb  = ws + O_PB;
    float* pm  = ws + O_PM;
    float* hf  = ws + O_HF;
    float* hb  = ws + O_HB;
    float* hd  = ws + O_HD;
    float* out = (float*)d_out;

    __nv_bfloat16* Aemb = abx + AB_EMB;
    __nv_bfloat16* Aenc = abx + AB_ENC;
    __nv_bfloat16* Ahf  = abx + AB_HF;
    __nv_bfloat16* Ahb  = abx + AB_HB;
    __nv_bfloat16* Ahd  = abx + AB_HD;
    __nv_bfloat16* Ax   = abx + AB_X;
    __nv_bfloat16* Ami  = abx + AB_MI;
    __nv_bfloat16* Atm  = abx + AB_TM;

    // batched weight conversion: one node for all 11 weights
    {
        WJobs jb;
        const float* Ws[NWJ]  = {enc_wx_f, enc_wx_b, enc_wh_f, enc_wh_b, enc_fc_w,
                                 attn_w, attn_w, dec_wx, dec_wh, max_w, out_w};
        const long long off[NWJ] = {(long long)WB_EXF, (long long)WB_EXB,
                                    (long long)WB_WHF, (long long)WB_WHB,
                                    (long long)WB_FC,  (long long)WB_AWH,
                                    (long long)WB_AWE, (long long)WB_DWX,
                                    (long long)WB_DWH, (long long)WB_MXW,
                                    (long long)WB_OUW};
        const int rs[NWJ]   = {EMBD, EMBD, HIDN, HIDN, HIDN, G3, G3, DXK, HIDN, MXK, MXO};
        const int co[NWJ]   = {0, 0, 0, 0, 0, 0, HIDN, 0, 0, 0, 0};
        const int Nn[NWJ]   = {3000, 3000, 3000, 3000, 1000, 1000, 1000, 3000, 3000, 1000, 30000};
        const int Kk[NWJ]   = {EMBD, EMBD, HIDN, HIDN, HIDN, HIDN, E2, DXK, HIDN, MXK, MXO};
        const int nw[NWJ]   = {NW_EX, NW_EX, NW_WH, NW_WH, NW_WH, NW_WH, NW_EN,
                               NW_X, NW_WH, NW_MI, NW_TM};
        int bacc = 0;
        for (int j = 0; j < NWJ; j++) {
            jb.W[j] = Ws[j]; jb.off[j] = off[j];
            jb.rs[j] = rs[j]; jb.co[j] = co[j];
            jb.N[j] = Nn[j]; jb.K[j] = Kk[j]; jb.nwin[j] = nw[j];
            jb.b0[j] = bacc;
            size_t tot = (size_t)(((Nn[j] + 127) >> 7) * 128) * (size_t)nw[j] * 64;
            bacc += (int)((tot + 255) / 256);
        }
        jb.b0[NWJ] = bacc;
        wconv_mega_k<<<bacc, 256>>>(jb, wb);
    }

    cudaMemsetAsync(abx, 0, AB_TOT * sizeof(__nv_bfloat16));
    cudaMemsetAsync(hf, 0, (size_t)2 * BB * HIDN * sizeof(float));  // hf+hb adjacent
    cudaMemsetAsync(out, 0, (size_t)BB * OUTV * sizeof(float));

    // ---------------- Encoder ----------------
    embed_split_k<<<up(S_LEN * BB * EMBD, 256), 256>>>(enc_emb, src, Aemb);
    tg2(mkt(Aemb, wb + WB_EXF, enc_bx_f, gxf, S_LEN * BB, G3, NW_EX, 1),
        mkt(Aemb, wb + WB_EXB, enc_bx_b, gxb, S_LEN * BB, G3, NW_EX, 1));

    for (int s = 0; s < S_LEN; s++) {
        int sb = S_LEN - 1 - s;
        tg2(mkt(Ahf, wb + WB_WHF, nullptr, pa, BB, G3, NW_WH, 4),
            mkt(Ahb, wb + WB_WHB, nullptr, pb, BB, G3, NW_WH, 4));
        gru_gate2_k<<<up(2 * BB * HIDN, 256), 256>>>(
            gxf + (size_t)s * BB * G3, gxb + (size_t)sb * BB * G3,
            pa, pb, enc_bh_f, enc_bh_b, hf, hb, Ahf, Ahb, enc, Aenc, s, sb);
    }

    tg1(mkt(Ahb, wb + WB_FC, nullptr, pa, BB, HIDN, NW_WH, 8));
    finalize_tanh_hd_k<<<up(BB * HIDN, 256), 256>>>(pa, enc_fc_b, hd, Ahd);
    // e_part + initial hq (dual)
    tg2(mkt(Aenc, wb + WB_AWE, nullptr, ep, S_LEN * BB, ATTD, NW_EN, 1),
        mkt(Ahd, wb + WB_AWH, nullptr, pa, BB, ATTD, NW_WH, 8));

    // ---------------- Decoder ----------------
    for (int t = 0; t < T_LEN - 1; t++) {
        attention_k<<<BB, 256>>>(pa, ep, attn_b, attn_v, enc, dec_emb, trg, t, Ax, Ami);
        // dec dual GEMM: split 8 each (critical path ~6 windows)
        tg2(mkt(Ax,  wb + WB_DWX, nullptr, pa, BB, G3, NW_X,  8),
            mkt(Ahd, wb + WB_DWH, nullptr, pb, BB, G3, NW_WH, 8));
        gru_gate_k<<<up(BB * HIDN, 256), 256>>>(pa, dec_bx, pb, dec_bh, hd, Ahd, Ami);
        // maxout split 16 + next-step hq split 8 (dual)
        tg2(mkt(Ami, wb + WB_MXW, nullptr, pm, BB, MX2, NW_MI, 16),
            mkt(Ahd, wb + WB_AWH, nullptr, pa, BB, ATTD, NW_WH, 8));
        finalize_max_k<<<up(BB * MXO, 256), 256>>>(pm, max_b, Atm);
        float* pred = out + (size_t)(t + 1) * BB * OUTV;
        tg1(mkt(Atm, wb + WB_OUW, out_b, pred, BB, OUTV, NW_TM, 1, 1));
    }
}

// round 16
// speedup vs baseline: 1.1061x; 1.0020x over previous
#include <cuda_runtime.h>
#include <cuda_bf16.h>
#include <math.h>
#include <stdint.h>

#define S_LEN 40
#define T_LEN 30
#define BB    64
#define EMBD  620
#define HIDN  1000
#define ATTD  1000
#define MXO   500
#define OUTV  30000
#define G3    3000
#define E2    2000
#define DXK   2620
#define MXK   3620
#define MX2   1000

// windows (64 K-cols each) per operand family
#define NW_EX  10
#define NW_WH  16
#define NW_EN  32
#define NW_X   41
#define NW_MI  57
#define NW_TM  8

#define TILE_E 8192
#define TILE_B 16384

// ---------------- fp32 workspace ----------------
static const size_t O_GXF = 0;
static const size_t O_GXB = O_GXF + (size_t)S_LEN*BB*G3;
static const size_t O_ENC = O_GXB + (size_t)S_LEN*BB*G3;
static const size_t O_EP  = O_ENC + (size_t)S_LEN*BB*E2;
static const size_t O_PA  = O_EP  + (size_t)S_LEN*BB*ATTD;
static const size_t O_PB  = O_PA  + (size_t)8*BB*G3;
static const size_t O_PM  = O_PB  + (size_t)8*BB*G3;
static const size_t O_HF  = O_PM  + (size_t)16*BB*MX2;
static const size_t O_HB  = O_HF  + (size_t)BB*HIDN;
static const size_t O_HD  = O_HB  + (size_t)BB*HIDN;
static const size_t ARENA = O_HD  + (size_t)BB*HIDN;

__device__ __align__(256) float g_ws[ARENA];
__device__ unsigned long long g_amax[BB];

// ---------------- tiled bf16 weight arena (tile = 16KB smem image) --------
static const size_t WB_EXF = 0;
static const size_t WB_EXB = WB_EXF + (size_t)24*NW_EX*3*TILE_E;
static const size_t WB_WHF = WB_EXB + (size_t)24*NW_EX*3*TILE_E;
static const size_t WB_WHB = WB_WHF + (size_t)24*NW_WH*3*TILE_E;
static const size_t WB_FC  = WB_WHB + (size_t)24*NW_WH*3*TILE_E;
static const size_t WB_AWH = WB_FC  + (size_t)8*NW_WH*3*TILE_E;
static const size_t WB_AWE = WB_AWH + (size_t)8*NW_WH*3*TILE_E;
static const size_t WB_DWX = WB_AWE + (size_t)8*NW_EN*3*TILE_E;
static const size_t WB_DWH = WB_DWX + (size_t)24*NW_X*3*TILE_E;
static const size_t WB_MXW = WB_DWH + (size_t)24*NW_WH*3*TILE_E;
static const size_t WB_OUW = WB_MXW + (size_t)8*NW_MI*3*TILE_E;
static const size_t WB_TOT = WB_OUW + (size_t)235*NW_TM*3*TILE_E;

__device__ __align__(256) __nv_bfloat16 g_wb[WB_TOT];

// ---------------- tiled bf16 activation arena ----------------
static const size_t AB_EMB = 0;
static const size_t AB_ENC = AB_EMB + (size_t)20*NW_EX*3*TILE_E;
static const size_t AB_HF  = AB_ENC + (size_t)20*NW_EN*3*TILE_E;
static const size_t AB_HB  = AB_HF  + (size_t)NW_WH*3*TILE_E;
static const size_t AB_HD  = AB_HB  + (size_t)NW_WH*3*TILE_E;
static const size_t AB_X   = AB_HD  + (size_t)NW_WH*3*TILE_E;
static const size_t AB_MI  = AB_X   + (size_t)NW_X*3*TILE_E;
static const size_t AB_TM  = AB_MI  + (size_t)NW_MI*3*TILE_E;
static const size_t AB_TOT = AB_TM  + (size_t)NW_TM*3*TILE_E;

__device__ __align__(256) __nv_bfloat16 g_ab[AB_TOT];

// ---------------- helpers ----------------
__device__ __forceinline__ uint32_t su32(const void* p)
{
    uint32_t a;
    asm("{ .reg .u64 t; cvta.to.shared.u64 t, %1; cvt.u32.u64 %0, t; }"
        : "=r"(a) : "l"(p));
    return a;
}
__device__ __forceinline__ uint64_t mkdesc(uint32_t addr)
{
    const uint64_t base = (uint64_t(2) << 61) | (uint64_t(1) << 46) |
                          (uint64_t(64) << 32) | (uint64_t(1) << 16);
    return base | ((uint64_t)(addr >> 4) & 0x3FFF);
}
__device__ __forceinline__ void mbar_init(uint32_t mb, uint32_t cnt)
{
    asm volatile("mbarrier.init.shared.b64 [%0], %1;" :: "r"(mb), "r"(cnt) : "memory");
}
__device__ __forceinline__ void mbar_wait(uint32_t mb, int parity)
{
    asm volatile(
        "{\n\t.reg .pred P;\n\t"
        "WL_%=:\n\t"
        "mbarrier.try_wait.parity.acquire.cta.shared::cta.b64 P, [%0], %1, 0x989680;\n\t"
        "@P bra.uni WD_%=;\n\t"
        "bra.uni WL_%=;\n\t"
        "WD_%=:\n\t}"
        :: "r"(mb), "r"(parity) : "memory");
}
__device__ __forceinline__ void expect_tx(uint32_t mb, uint32_t bytes)
{
    asm volatile("mbarrier.arrive.expect_tx.shared.b64 _, [%0], %1;"
                 :: "r"(mb), "r"(bytes) : "memory");
}
__device__ __forceinline__ void bulk_g2s(uint32_t dst, const void* src, uint32_t bytes,
                                         uint32_t mb)
{
    asm volatile(
        "cp.async.bulk.shared::cluster.global.mbarrier::complete_tx::bytes [%0], [%1], %2, [%3];"
        :: "r"(dst), "l"(src), "r"(bytes), "r"(mb) : "memory");
}
__device__ __forceinline__ void mma_bf16_ss(uint32_t d, uint64_t ad, uint64_t bd,
                                            uint32_t idesc, uint32_t acc)
{
    asm volatile(
        "{\n\t.reg .pred p;\n\t"
        "setp.ne.u32 p, %5, 0;\n\t"
        "tcgen05.mma.cta_group::1.kind::f16 [%0], %1, %2, %3, {%4,%4,%4,%4}, p;\n\t}"
        :: "r"(d), "l"(ad), "l"(bd), "r"(idesc), "r"(0u), "r"(acc) : "memory");
}
__device__ __forceinline__ void tc_commit(uint32_t mb)
{
    asm volatile(
        "tcgen05.commit.cta_group::1.mbarrier::arrive::one.shared::cluster.b64 [%0];"
        :: "r"(mb) : "memory");
}
#define LDTM_X32(r, ta) \
    asm volatile( \
        "tcgen05.ld.sync.aligned.32x32b.x32.b32 " \
        "{%0,%1,%2,%3,%4,%5,%6,%7,%8,%9,%10,%11,%12,%13,%14,%15," \
        "%16,%17,%18,%19,%20,%21,%22,%23,%24,%25,%26,%27,%28,%29,%30,%31}, [%32];" \
        : "=r"((r)[0]),"=r"((r)[1]),"=r"((r)[2]),"=r"((r)[3]), \
          "=r"((r)[4]),"=r"((r)[5]),"=r"((r)[6]),"=r"((r)[7]), \
          "=r"((r)[8]),"=r"((r)[9]),"=r"((r)[10]),"=r"((r)[11]), \
          "=r"((r)[12]),"=r"((r)[13]),"=r"((r)[14]),"=r"((r)[15]), \
          "=r"((r)[16]),"=r"((r)[17]),"=r"((r)[18]),"=r"((r)[19]), \
          "=r"((r)[20]),"=r"((r)[21]),"=r"((r)[22]),"=r"((r)[23]), \
          "=r"((r)[24]),"=r"((r)[25]),"=r"((r)[26]),"=r"((r)[27]), \
          "=r"((r)[28]),"=r"((r)[29]),"=r"((r)[30]),"=r"((r)[31]) \
        : "r"(ta))

#define TG_IDESC 0x8200490u
// single-buffered: 6 tiles -> 97KB => 2 CTAs/SM co-resident
#define TG_SMEM  (1024 + 6 * TILE_B)

__device__ __forceinline__ size_t toff(int nwin, int R, int k)
{
    uint32_t inner = (uint32_t)((R & 127) * 128 + (k & 63) * 2);
    inner ^= (inner >> 3) & 0x70;
    return ((size_t)(((R >> 7) * nwin + (k >> 6)) * 3) << 13) + (inner >> 1);
}
__device__ __forceinline__ void wsplit3_t(__nv_bfloat16* base, int nwin, int R, int k, float a)
{
    __nv_bfloat16 h = __float2bfloat16(a);
    float r1 = a - __bfloat162float(h);
    __nv_bfloat16 m = __float2bfloat16(r1);
    float r2 = r1 - __bfloat162float(m);
    size_t o = toff(nwin, R, k);
    base[o] = h;
    base[o + TILE_E] = m;
    base[o + 2 * TILE_E] = __float2bfloat16(r2);
}
__device__ __forceinline__ unsigned long long amax_key(float v, int idx)
{
    unsigned u = __float_as_uint(v);
    u = (u & 0x80000000u) ? ~u : (u | 0x80000000u);
    return ((unsigned long long)u << 32) | (unsigned)(OUTV - idx);
}

// ---------------- batched weight conversion: all 11 jobs, one node --------
#define NWJ 11
struct WJobs {
    const float* W[NWJ];
    long long    off[NWJ];
    int rs[NWJ], co[NWJ], N[NWJ], K[NWJ], nwin[NWJ];
    int b0[NWJ + 1];
};

__global__ void wconv_mega_k(WJobs jb, __nv_bfloat16* __restrict__ base)
{
    const int blk = blockIdx.x;
    int j = 0;
    while (j < NWJ - 1 && blk >= jb.b0[j + 1]) j++;
    const int nwin = jb.nwin[j];
    const int Kp = nwin * 64;
    const int NT = (jb.N[j] + 127) >> 7;
    const size_t tot = (size_t)NT * 128 * Kp;
    size_t i = (size_t)(blk - jb.b0[j]) * 256 + threadIdx.x;
    if (i >= tot) return;
    int R = (int)(i / Kp), k = (int)(i - (size_t)R * Kp);
    float a = (R < jb.N[j] && k < jb.K[j])
            ? jb.W[j][(size_t)R * jb.rs[j] + jb.co[j] + k] : 0.f;
    wsplit3_t(base + jb.off[j], nwin, R, k, a);
}

// ---------------------------------------------------------------------------
// tcgen05 GEMM, TMA-bulk staged, single-buffered (2 CTAs/SM overlap).
// For jobs with M <= 64: A parts staged as 8KB (rows 0-63 only); upper
// halves of the A slots zeroed once per CTA (identical math, -25% traffic).
// amax=1: fused per-row argmax via atomicMax into g_amax.
// ---------------------------------------------------------------------------
struct TG {
    const __nv_bfloat16* Ab;
    const __nv_bfloat16* Wb;
    const float* bias;
    float* C;
    int M, N, nwin, split, amax;
};

__global__ void __launch_bounds__(128) tgemm_k(TG g0, TG g1, int ua)
{
#if defined(__CUDA_ARCH_FEAT_SM103_ALL)
    const int u = blockIdx.x;
    const TG g = (u < ua) ? g0 : g1;
    int v = (u < ua) ? u : u - ua;
    const int ntn = (g.N + 127) >> 7;
    const int z = v % g.split;
    const int rest = v / g.split;
    const int nt = rest % ntn;
    const int mt = rest / ntn;
    const int nwin = g.nwin;
    const int kcw = (nwin + g.split - 1) / g.split;
    const int w0 = z * kcw;
    int w1 = w0 + kcw; if (w1 > nwin) w1 = nwin;
    const int nw = (w1 > w0) ? (w1 - w0) : 0;
    const int m0 = mt << 7, n0 = nt << 7;
    const bool fin = (g.split == 1);
    float* Cz = g.C + (size_t)z * g.M * g.N;

    const int tid = threadIdx.x;
    const int wid = tid >> 5, lane = tid & 31;
    const int ha = (g.M <= 64) ? 1 : 0;          // half-A staging
    const uint32_t abytes = ha ? 8192u : 16384u;

    extern __shared__ __align__(16) char dyn[];
    const uint32_t dbase = (su32(dyn) + 1023u) & ~1023u;

    __shared__ __align__(8) unsigned long long s_bar[2];  // ld, mm
    __shared__ uint32_t s_tptr;

    if (wid == 0) {
        asm volatile("tcgen05.alloc.cta_group::1.sync.aligned.shared::cta.b32 [%0], %1;"
                     :: "r"(su32(&s_tptr)), "r"(128u) : "memory");
        asm volatile("tcgen05.relinquish_alloc_permit.cta_group::1.sync.aligned;");
    }
    if (tid == 0) { mbar_init(su32(&s_bar[0]), 1); mbar_init(su32(&s_bar[1]), 1); }

    // zero upper halves of the 3 A slots (rows 64-127) when half-staging
    if (ha && nw > 0) {
#pragma unroll
        for (int p = 0; p < 3; p++) {
            uint32_t basea = dbase + (uint32_t)p * TILE_B + 8192u;
            for (uint32_t o = (uint32_t)tid * 16u; o < 8192u; o += 128u * 16u)
                asm volatile("st.shared.v4.b32 [%0], {%1,%1,%1,%1};"
                             :: "r"(basea + o), "r"(0u) : "memory");
        }
        asm volatile("fence.proxy.async.shared::cta;" ::: "memory");
    }
    __syncthreads();
    const uint32_t tmem = s_tptr;

    if (nw > 0 && tid == 0) {
        const uint32_t ld = su32(&s_bar[0]);
        const uint32_t mm = su32(&s_bar[1]);
        int pl = 0, pq = 0;
        const char* At = (const char*)g.Ab;
        const char* Bt = (const char*)g.Wb;
        const int segA[6] = {0, 1, 2, 0, 1, 0};
        const int segB[6] = {0, 0, 0, 1, 1, 2};
        bool first = true;
        const uint32_t txb = 3u * abytes + 3u * TILE_B;

        for (int i = 0; i < nw; i++) {
            const int w = w0 + i;
            expect_tx(ld, txb);
            const size_t abase = ((size_t)((mt * nwin + w) * 3)) * TILE_B;
            const size_t bbase = ((size_t)((nt * nwin + w) * 3)) * TILE_B;
#pragma unroll
            for (int p = 0; p < 3; p++) {
                bulk_g2s(dbase + (uint32_t)p * TILE_B,
                         At + abase + (size_t)p * TILE_B, abytes, ld);
                bulk_g2s(dbase + (uint32_t)(3 + p) * TILE_B,
                         Bt + bbase + (size_t)p * TILE_B, TILE_B, ld);
            }
            mbar_wait(ld, pl); pl ^= 1;
#pragma unroll
            for (int s = 0; s < 6; s++) {
                uint64_t ad = mkdesc(dbase + (uint32_t)segA[s] * TILE_B);
                uint64_t bd = mkdesc(dbase + (uint32_t)(3 + segB[s]) * TILE_B);
#pragma unroll
                for (int q = 0; q < 4; q++) {
                    mma_bf16_ss(tmem, ad + 2 * q, bd + 2 * q, TG_IDESC, first ? 0u : 1u);
                    first = false;
                }
            }
            tc_commit(mm);
            mbar_wait(mm, pq); pq ^= 1;   // single buffer: drain before reuse
        }
    }
    __syncthreads();
    asm volatile("tcgen05.fence::after_thread_sync;" ::: "memory");

    // epilogue
    const int r = m0 + wid * 32 + lane;
    if (nw == 0) {
        if (r < g.M)
            for (int c0 = 0; c0 < 128; c0++) {
                int c = n0 + c0;
                if (c < g.N) Cz[(size_t)r * g.N + c] = (fin && g.bias) ? g.bias[c] : 0.f;
            }
    } else {
        float bestv = -1e30f; int besti = 0;
#pragma unroll
        for (int base = 0; base < 128; base += 32) {
            uint32_t regs[32];
            LDTM_X32(regs, tmem + base);
            asm volatile("tcgen05.wait::ld.sync.aligned;" ::: "memory");
            if (r < g.M) {
#pragma unroll
                for (int q = 0; q < 32; q++) {
                    int c = n0 + base + q;
                    if (c < g.N) {
                        float vv = __uint_as_float(regs[q]);
                        if (fin && g.bias) vv += g.bias[c];
                        Cz[(size_t)r * g.N + c] = vv;
                        if (g.amax && (vv > bestv || (vv == bestv && c < besti))) {
                            bestv = vv; besti = c;
                        }
                    }
                }
            }
        }
        if (g.amax && r < g.M)
            atomicMax(&g_amax[r], amax_key(bestv, besti));
    }
    __syncthreads();
    if (wid == 0)
        asm volatile("tcgen05.dealloc.cta_group::1.sync.aligned.b32 %0, %1;"
                     :: "r"(tmem), "r"(128u));
#else
    (void)g0; (void)g1; (void)ua;   // compile-only stub (runtime picks sm_103a cubin)
#endif
}

// ---------------- elementwise / fused kernels ----------------
__global__ void embed_split_k(const float* __restrict__ table, const int* __restrict__ idx,
                              __nv_bfloat16* __restrict__ Ab)
{
    int i = blockIdx.x * blockDim.x + threadIdx.x;
    if (i >= S_LEN * BB * EMBD) return;
    int r = i / EMBD, e = i - r * EMBD;
    wsplit3_t(Ab, NW_EX, r, e, table[(size_t)idx[r] * EMBD + e]);
}

__global__ void gru_gate2_k(const float* __restrict__ gxf, const float* __restrict__ gxb,
                            const float* __restrict__ pf, const float* __restrict__ pb,
                            const float* __restrict__ bhf, const float* __restrict__ bhb,
                            float* __restrict__ hf, float* __restrict__ hb,
                            __nv_bfloat16* __restrict__ Ahf,
                            __nv_bfloat16* __restrict__ Ahb,
                            float* __restrict__ enc,
                            __nv_bfloat16* __restrict__ Aenc,
                            int sf, int sb)
{
    int i = blockIdx.x * blockDim.x + threadIdx.x;
    if (i >= 2 * BB * HIDN) return;
    int dir = (i >= BB * HIDN);
    int ii = dir ? i - BB * HIDN : i;
    int b = ii / HIDN, j = ii - b * HIDN;
    const float* gx = (dir ? gxb : gxf) + (size_t)b * G3;
    const float* phh = dir ? pb : pf;
    const float* bh = dir ? bhb : bhf;
    float* h = dir ? hb : hf;

    float xr = gx[j], xz = gx[HIDN + j], xn = gx[2 * HIDN + j];
    float hr = bh[j], hz = bh[HIDN + j], hn = bh[2 * HIDN + j];
    for (int z = 0; z < 4; z++) {
        const float* q = phh + ((size_t)z * BB + b) * G3;
        hr += q[j]; hz += q[HIDN + j]; hn += q[2 * HIDN + j];
    }
    float r  = 1.f / (1.f + expf(-(xr + hr)));
    float zz = 1.f / (1.f + expf(-(xz + hz)));
    float n  = tanhf(xn + r * hn);
    float h2 = (1.f - zz) * n + zz * h[ii];
    h[ii] = h2;
    wsplit3_t(dir ? Ahb : Ahf, NW_WH, b, j, h2);
    int row = (dir ? sb : sf) * BB + b;
    int col = dir ? HIDN + j : j;
    enc[(size_t)row * E2 + col] = h2;
    wsplit3_t(Aenc, NW_EN, row, col, h2);
}

__global__ void finalize_tanh_hd_k(const float* __restrict__ parts,
                                   const float* __restrict__ bias,
                                   float* __restrict__ hd,
                                   __nv_bfloat16* __restrict__ Ahd)
{
    int i = blockIdx.x * blockDim.x + threadIdx.x;
    if (i >= BB * HIDN) return;
    int b = i / HIDN, j = i - b * HIDN;
    float v = 0.f;
    for (int z = 0; z < 8; z++) v += parts[(size_t)z * BB * HIDN + i];
    v = tanhf(v + bias[j]);
    hd[i] = v;
    wsplit3_t(Ahd, NW_WH, b, j, v);
}

// fused attention: token from trg (t==0) or fused argmax of previous step
__global__ void attention_k(const float* __restrict__ pa,
                            const float* __restrict__ ep,
                            const float* __restrict__ ab,
                            const float* __restrict__ av,
                            const float* __restrict__ enc,
                            const float* __restrict__ demb,
                            const int*   __restrict__ trg, int t,
                            __nv_bfloat16* __restrict__ Ax,
                            __nv_bfloat16* __restrict__ Ami)
{
    const int b = blockIdx.x;
    const int tid = threadIdx.x;
    const int wid = tid >> 5, lane = tid & 31;
    __shared__ float hqs[ATTD];
    __shared__ float al[S_LEN];

    for (int a = tid; a < ATTD; a += 256) {
        float s = 0.f;
#pragma unroll
        for (int z = 0; z < 8; z++) s += pa[((size_t)z * BB + b) * ATTD + a];
        hqs[a] = s;
    }
    __syncthreads();

    for (int s = wid; s < S_LEN; s += 8) {
        const float* eprow = ep + ((size_t)s * BB + b) * ATTD;
        float e = 0.f;
        for (int a = lane; a < ATTD; a += 32)
            e += av[a] * tanhf(hqs[a] + eprow[a] + ab[a]);
#pragma unroll
        for (int o = 16; o; o >>= 1) e += __shfl_down_sync(0xffffffffu, e, o);
        if (lane == 0) al[s] = e;
    }
    __syncthreads();

    if (tid == 0) {
        float m = -1e30f;
        for (int s = 0; s < S_LEN; s++) m = fmaxf(m, al[s]);
        float sum = 0.f;
        for (int s = 0; s < S_LEN; s++) { float e = expf(al[s] - m); al[s] = e; sum += e; }
        float inv = 1.f / sum;
        for (int s = 0; s < S_LEN; s++) al[s] *= inv;
    }
    __syncthreads();

    for (int hc = tid; hc < E2; hc += 256) {
        float c = 0.f;
        for (int s = 0; s < S_LEN; s++)
            c += al[s] * enc[((size_t)s * BB + b) * E2 + hc];
        wsplit3_t(Ax, NW_X, b, EMBD + hc, c);
        wsplit3_t(Ami, NW_MI, b, HIDN + hc, c);
    }
    const int tok = (t == 0) ? trg[b]
                  : (int)(OUTV - (unsigned)(g_amax[b] & 0xffffffffu));
    for (int e = tid; e < EMBD; e += 256) {
        float vv = demb[(size_t)tok * EMBD + e];
        wsplit3_t(Ax, NW_X, b, e, vv);
        wsplit3_t(Ami, NW_MI, b, G3 + e, vv);
    }
}

// decoder GRU gate (8 partials per operand)
__global__ void gru_gate_k(const float* __restrict__ gx, const float* __restrict__ bx,
                           const float* __restrict__ gh, const float* __restrict__ bh,
                           float* __restrict__ h,
                           __nv_bfloat16* __restrict__ Ahd,
                           __nv_bfloat16* __restrict__ Ami)
{
    int i = blockIdx.x * blockDim.x + threadIdx.x;
    if (i >= BB * HIDN) return;
    int b = i / HIDN, j = i - b * HIDN;
    float xr = bx[j], xz = bx[HIDN + j], xn = bx[2 * HIDN + j];
    float hr = bh[j], hz = bh[HIDN + j], hn = bh[2 * HIDN + j];
    for (int z = 0; z < 8; z++) {
        const float* q1 = gx + ((size_t)z * BB + b) * G3;
        const float* q2 = gh + ((size_t)z * BB + b) * G3;
        xr += q1[j]; xz += q1[HIDN + j]; xn += q1[2 * HIDN + j];
        hr += q2[j]; hz += q2[HIDN + j]; hn += q2[2 * HIDN + j];
    }
    float r  = 1.f / (1.f + expf(-(xr + hr)));
    float zz = 1.f / (1.f + expf(-(xz + hz)));
    float n  = tanhf(xn + r * hn);
    float h2 = (1.f - zz) * n + zz * h[i];
    h[i] = h2;
    wsplit3_t(Ahd, NW_WH, b, j, h2);
    wsplit3_t(Ami, NW_MI, b, j, h2);
}

// maxout finalize (16 partials) + zero argmax accumulator
__global__ void finalize_max_k(const float* __restrict__ pm,
                               const float* __restrict__ bias,
                               __nv_bfloat16* __restrict__ Atm)
{
    int i = blockIdx.x * blockDim.x + threadIdx.x;
    if (i < BB) g_amax[i] = 0ull;
    if (i >= BB * MXO) return;
    int b = i / MXO, o = i - b * MXO;
    float v0 = bias[2 * o], v1 = bias[2 * o + 1];
    for (int z = 0; z < 16; z++) {
        const float* q = pm + ((size_t)z * BB + b) * MX2;
        v0 += q[2 * o]; v1 += q[2 * o + 1];
    }
    wsplit3_t(Atm, NW_TM, b, o, fmaxf(v0, v1));
}

// ---------------- host ----------------
static inline int up(int n, int b) { return (n + b - 1) / b; }

static inline TG mkt(const __nv_bfloat16* Ab, const __nv_bfloat16* Wb,
                     const float* bias, float* C, int M, int N, int nwin,
                     int split, int amax = 0)
{
    TG g; g.Ab = Ab; g.Wb = Wb; g.bias = bias; g.C = C;
    g.M = M; g.N = N; g.nwin = nwin; g.split = split; g.amax = amax;
    return g;
}
static inline int units(const TG& g)
{
    return ((g.M + 127) >> 7) * ((g.N + 127) >> 7) * g.split;
}
static inline void tg1(const TG& g)
{
    tgemm_k<<<units(g), 128, TG_SMEM>>>(g, g, units(g));
}
static inline void tg2(const TG& a, const TG& b)
{
    tgemm_k<<<units(a) + units(b), 128, TG_SMEM>>>(a, b, units(a));
}

extern "C" void kernel_launch(void* const* d_in, const int* in_sizes, int n_in,
                              void* d_out, int out_size)
{
    (void)in_sizes; (void)n_in; (void)out_size;
    const int*   src      = (const int*)  d_in[0];
    const int*   trg      = (const int*)  d_in[1];
    const float* enc_emb  = (const float*)d_in[2];
    const float* enc_wx_f = (const float*)d_in[3];
    const float* enc_wh_f = (const float*)d_in[4];
    const float* enc_bx_f = (const float*)d_in[5];
    const float* enc_bh_f = (const float*)d_in[6];
    const float* enc_wx_b = (const float*)d_in[7];
    const float* enc_wh_b = (const float*)d_in[8];
    const float* enc_bx_b = (const float*)d_in[9];
    const float* enc_bh_b = (const float*)d_in[10];
    const float* enc_fc_w = (const float*)d_in[11];
    const float* enc_fc_b = (const float*)d_in[12];
    const float* attn_w   = (const float*)d_in[13];
    const float* attn_b   = (const float*)d_in[14];
    const float* attn_v   = (const float*)d_in[15];
    const float* dec_emb  = (const float*)d_in[16];
    const float* dec_wx   = (const float*)d_in[17];
    const float* dec_wh   = (const float*)d_in[18];
    const float* dec_bx   = (const float*)d_in[19];
    const float* dec_bh   = (const float*)d_in[20];
    const float* max_w    = (const float*)d_in[21];
    const float* max_b    = (const float*)d_in[22];
    const float* out_w    = (const float*)d_in[23];
    const float* out_b    = (const float*)d_in[24];

    cudaFuncSetAttribute(tgemm_k, cudaFuncAttributeMaxDynamicSharedMemorySize, TG_SMEM);

    float* ws = nullptr;
    __nv_bfloat16* wb = nullptr; __nv_bfloat16* abx = nullptr;
    cudaGetSymbolAddress((void**)&ws, g_ws);
    cudaGetSymbolAddress((void**)&wb, g_wb);
    cudaGetSymbolAddress((void**)&abx, g_ab);

    float* gxf = ws + O_GXF;
    float* gxb = ws + O_GXB;
    float* enc = ws + O_ENC;
    float* ep  = ws + O_EP;
    float* pa  = ws + O_PA;
    float* pb  = ws + O_PB;
    float* pm  = ws + O_PM;
    float* hf  = ws + O_HF;
    float* hb  = ws + O_HB;
    float* hd  = ws + O_HD;
    float* out = (float*)d_out;

    __nv_bfloat16* Aemb = abx + AB_EMB;
    __nv_bfloat16* Aenc = abx + AB_ENC;
    __nv_bfloat16* Ahf  = abx + AB_HF;
    __nv_bfloat16* Ahb  = abx + AB_HB;
    __nv_bfloat16* Ahd  = abx + AB_HD;
    __nv_bfloat16* Ax   = abx + AB_X;
    __nv_bfloat16* Ami  = abx + AB_MI;
    __nv_bfloat16* Atm  = abx + AB_TM;

    // batched weight conversion: one node for all 11 weights
    {
        WJobs jb;
        const float* Ws[NWJ]  = {enc_wx_f, enc_wx_b, enc_wh_f, enc_wh_b, enc_fc_w,
                                 attn_w, attn_w, dec_wx, dec_wh, max_w, out_w};
        const long long off[NWJ] = {(long long)WB_EXF, (long long)WB_EXB,
                                    (long long)WB_WHF, (long long)WB_WHB,
                                    (long long)WB_FC,  (long long)WB_AWH,
                                    (long long)WB_AWE, (long long)WB_DWX,
                                    (long long)WB_DWH, (long long)WB_MXW,
                                    (long long)WB_OUW};
        const int rs[NWJ]   = {EMBD, EMBD, HIDN, HIDN, HIDN, G3, G3, DXK, HIDN, MXK, MXO};
        const int co[NWJ]   = {0, 0, 0, 0, 0, 0, HIDN, 0, 0, 0, 0};
        const int Nn[NWJ]   = {3000, 3000, 3000, 3000, 1000, 1000, 1000, 3000, 3000, 1000, 30000};
        const int Kk[NWJ]   = {EMBD, EMBD, HIDN, HIDN, HIDN, HIDN, E2, DXK, HIDN, MXK, MXO};
        const int nw[NWJ]   = {NW_EX, NW_EX, NW_WH, NW_WH, NW_WH, NW_WH, NW_EN,
                               NW_X, NW_WH, NW_MI, NW_TM};
        int bacc = 0;
        for (int j = 0; j < NWJ; j++) {
            jb.W[j] = Ws[j]; jb.off[j] = off[j];
            jb.rs[j] = rs[j]; jb.co[j] = co[j];
            jb.N[j] = Nn[j]; jb.K[j] = Kk[j]; jb.nwin[j] = nw[j];
            jb.b0[j] = bacc;
            size_t tot = (size_t)(((Nn[j] + 127) >> 7) * 128) * (size_t)nw[j] * 64;
            bacc += (int)((tot + 255) / 256);
        }
        jb.b0[NWJ] = bacc;
        wconv_mega_k<<<bacc, 256>>>(jb, wb);
    }

    cudaMemsetAsync(abx, 0, AB_TOT * sizeof(__nv_bfloat16));
    cudaMemsetAsync(hf, 0, (size_t)2 * BB * HIDN * sizeof(float));  // hf+hb adjacent
    cudaMemsetAsync(out, 0, (size_t)BB * OUTV * sizeof(float));

    // ---------------- Encoder ----------------
    embed_split_k<<<up(S_LEN * BB * EMBD, 256), 256>>>(enc_emb, src, Aemb);
    tg2(mkt(Aemb, wb + WB_EXF, enc_bx_f, gxf, S_LEN * BB, G3, NW_EX, 1),
        mkt(Aemb, wb + WB_EXB, enc_bx_b, gxb, S_LEN * BB, G3, NW_EX, 1));

    for (int s = 0; s < S_LEN; s++) {
        int sb = S_LEN - 1 - s;
        tg2(mkt(Ahf, wb + WB_WHF, nullptr, pa, BB, G3, NW_WH, 4),
            mkt(Ahb, wb + WB_WHB, nullptr, pb, BB, G3, NW_WH, 4));
        gru_gate2_k<<<up(2 * BB * HIDN, 256), 256>>>(
            gxf + (size_t)s * BB * G3, gxb + (size_t)sb * BB * G3,
            pa, pb, enc_bh_f, enc_bh_b, hf, hb, Ahf, Ahb, enc, Aenc, s, sb);
    }

    tg1(mkt(Ahb, wb + WB_FC, nullptr, pa, BB, HIDN, NW_WH, 8));
    finalize_tanh_hd_k<<<up(BB * HIDN, 256), 256>>>(pa, enc_fc_b, hd, Ahd);
    // e_part + initial hq (dual)
    tg2(mkt(Aenc, wb + WB_AWE, nullptr, ep, S_LEN * BB, ATTD, NW_EN, 1),
        mkt(Ahd, wb + WB_AWH, nullptr, pa, BB, ATTD, NW_WH, 8));

    // ---------------- Decoder ----------------
    for (int t = 0; t < T_LEN - 1; t++) {
        attention_k<<<BB, 256>>>(pa, ep, attn_b, attn_v, enc, dec_emb, trg, t, Ax, Ami);
        // dec dual GEMM: split 8 each
        tg2(mkt(Ax,  wb + WB_DWX, nullptr, pa, BB, G3, NW_X,  8),
            mkt(Ahd, wb + WB_DWH, nullptr, pb, BB, G3, NW_WH, 8));
        gru_gate_k<<<up(BB * HIDN, 256), 256>>>(pa, dec_bx, pb, dec_bh, hd, Ahd, Ami);
        // maxout split 16 + next-step hq split 8 (dual)
        tg2(mkt(Ami, wb + WB_MXW, nullptr, pm, BB, MX2, NW_MI, 16),
            mkt(Ahd, wb + WB_AWH, nullptr, pa, BB, ATTD, NW_WH, 8));
        finalize_max_k<<<up(BB * MXO, 256), 256>>>(pm, max_b, Atm);
        float* pred = out + (size_t)(t + 1) * BB * OUTV;
        tg1(mkt(Atm, wb + WB_OUW, out_b, pred, BB, OUTV, NW_TM, 1, 1));
    }
}

// round 17
// speedup vs baseline: 1.1408x; 1.0314x over previous
#include <cuda_runtime.h>
#include <cuda_bf16.h>
#include <math.h>
#include <stdint.h>

#define S_LEN 40
#define T_LEN 30
#define BB    64
#define EMBD  620
#define HIDN  1000
#define ATTD  1000
#define MXO   500
#define OUTV  30000
#define G3    3000
#define E2    2000
#define DXK   2620
#define MXK   3620
#define MX2   1000

// windows (64 K-cols each) per operand family
#define NW_EX  10
#define NW_WH  16
#define NW_EN  32
#define NW_X   41
#define NW_MI  57
#define NW_TM  8

#define TILE_E 8192
#define TILE_B 16384

// ---------------- fp32 workspace ----------------
static const size_t O_GXF = 0;
static const size_t O_GXB = O_GXF + (size_t)S_LEN*BB*G3;
static const size_t O_ENC = O_GXB + (size_t)S_LEN*BB*G3;
static const size_t O_EP  = O_ENC + (size_t)S_LEN*BB*E2;
static const size_t O_PA  = O_EP  + (size_t)S_LEN*BB*ATTD;
static const size_t O_PB  = O_PA  + (size_t)8*BB*G3;
static const size_t O_PM  = O_PB  + (size_t)8*BB*G3;
static const size_t O_HF  = O_PM  + (size_t)16*BB*MX2;
static const size_t O_HB  = O_HF  + (size_t)BB*HIDN;
static const size_t O_HD  = O_HB  + (size_t)BB*HIDN;
static const size_t ARENA = O_HD  + (size_t)BB*HIDN;

__device__ __align__(256) float g_ws[ARENA];
__device__ unsigned long long g_amax[BB];

// ---------------- tiled bf16 weight arena (tile = 16KB smem image) --------
static const size_t WB_EXF = 0;
static const size_t WB_EXB = WB_EXF + (size_t)24*NW_EX*3*TILE_E;
static const size_t WB_WHF = WB_EXB + (size_t)24*NW_EX*3*TILE_E;
static const size_t WB_WHB = WB_WHF + (size_t)24*NW_WH*3*TILE_E;
static const size_t WB_FC  = WB_WHB + (size_t)24*NW_WH*3*TILE_E;
static const size_t WB_AWH = WB_FC  + (size_t)8*NW_WH*3*TILE_E;
static const size_t WB_AWE = WB_AWH + (size_t)8*NW_WH*3*TILE_E;
static const size_t WB_DWX = WB_AWE + (size_t)8*NW_EN*3*TILE_E;
static const size_t WB_DWH = WB_DWX + (size_t)24*NW_X*3*TILE_E;
static const size_t WB_MXW = WB_DWH + (size_t)24*NW_WH*3*TILE_E;
static const size_t WB_OUW = WB_MXW + (size_t)8*NW_MI*3*TILE_E;
static const size_t WB_TOT = WB_OUW + (size_t)235*NW_TM*3*TILE_E;

__device__ __align__(256) __nv_bfloat16 g_wb[WB_TOT];

// ---------------- tiled bf16 activation arena ----------------
static const size_t AB_EMB = 0;
static const size_t AB_ENC = AB_EMB + (size_t)20*NW_EX*3*TILE_E;
static const size_t AB_HF  = AB_ENC + (size_t)20*NW_EN*3*TILE_E;
static const size_t AB_HB  = AB_HF  + (size_t)NW_WH*3*TILE_E;
static const size_t AB_HD  = AB_HB  + (size_t)NW_WH*3*TILE_E;
static const size_t AB_X   = AB_HD  + (size_t)NW_WH*3*TILE_E;
static const size_t AB_MI  = AB_X   + (size_t)NW_X*3*TILE_E;
static const size_t AB_TM  = AB_MI  + (size_t)NW_MI*3*TILE_E;
static const size_t AB_TOT = AB_TM  + (size_t)NW_TM*3*TILE_E;

__device__ __align__(256) __nv_bfloat16 g_ab[AB_TOT];

// ---------------- helpers ----------------
__device__ __forceinline__ uint32_t su32(const void* p)
{
    uint32_t a;
    asm("{ .reg .u64 t; cvta.to.shared.u64 t, %1; cvt.u32.u64 %0, t; }"
        : "=r"(a) : "l"(p));
    return a;
}
__device__ __forceinline__ uint64_t mkdesc(uint32_t addr)
{
    const uint64_t base = (uint64_t(2) << 61) | (uint64_t(1) << 46) |
                          (uint64_t(64) << 32) | (uint64_t(1) << 16);
    return base | ((uint64_t)(addr >> 4) & 0x3FFF);
}
__device__ __forceinline__ void mbar_init(uint32_t mb, uint32_t cnt)
{
    asm volatile("mbarrier.init.shared.b64 [%0], %1;" :: "r"(mb), "r"(cnt) : "memory");
}
__device__ __forceinline__ void mbar_wait(uint32_t mb, int parity)
{
    asm volatile(
        "{\n\t.reg .pred P;\n\t"
        "WL_%=:\n\t"
        "mbarrier.try_wait.parity.acquire.cta.shared::cta.b64 P, [%0], %1, 0x989680;\n\t"
        "@P bra.uni WD_%=;\n\t"
        "bra.uni WL_%=;\n\t"
        "WD_%=:\n\t}"
        :: "r"(mb), "r"(parity) : "memory");
}
__device__ __forceinline__ void expect_tx(uint32_t mb, uint32_t bytes)
{
    asm volatile("mbarrier.arrive.expect_tx.shared.b64 _, [%0], %1;"
                 :: "r"(mb), "r"(bytes) : "memory");
}
__device__ __forceinline__ void bulk_g2s(uint32_t dst, const void* src, uint32_t bytes,
                                         uint32_t mb)
{
    asm volatile(
        "cp.async.bulk.shared::cluster.global.mbarrier::complete_tx::bytes [%0], [%1], %2, [%3];"
        :: "r"(dst), "l"(src), "r"(bytes), "r"(mb) : "memory");
}
__device__ __forceinline__ void mma_bf16_ss(uint32_t d, uint64_t ad, uint64_t bd,
                                            uint32_t idesc, uint32_t acc)
{
    asm volatile(
        "{\n\t.reg .pred p;\n\t"
        "setp.ne.u32 p, %5, 0;\n\t"
        "tcgen05.mma.cta_group::1.kind::f16 [%0], %1, %2, %3, {%4,%4,%4,%4}, p;\n\t}"
        :: "r"(d), "l"(ad), "l"(bd), "r"(idesc), "r"(0u), "r"(acc) : "memory");
}
__device__ __forceinline__ void tc_commit(uint32_t mb)
{
    asm volatile(
        "tcgen05.commit.cta_group::1.mbarrier::arrive::one.shared::cluster.b64 [%0];"
        :: "r"(mb) : "memory");
}
#define LDTM_X32(r, ta) \
    asm volatile( \
        "tcgen05.ld.sync.aligned.32x32b.x32.b32 " \
        "{%0,%1,%2,%3,%4,%5,%6,%7,%8,%9,%10,%11,%12,%13,%14,%15," \
        "%16,%17,%18,%19,%20,%21,%22,%23,%24,%25,%26,%27,%28,%29,%30,%31}, [%32];" \
        : "=r"((r)[0]),"=r"((r)[1]),"=r"((r)[2]),"=r"((r)[3]), \
          "=r"((r)[4]),"=r"((r)[5]),"=r"((r)[6]),"=r"((r)[7]), \
          "=r"((r)[8]),"=r"((r)[9]),"=r"((r)[10]),"=r"((r)[11]), \
          "=r"((r)[12]),"=r"((r)[13]),"=r"((r)[14]),"=r"((r)[15]), \
          "=r"((r)[16]),"=r"((r)[17]),"=r"((r)[18]),"=r"((r)[19]), \
          "=r"((r)[20]),"=r"((r)[21]),"=r"((r)[22]),"=r"((r)[23]), \
          "=r"((r)[24]),"=r"((r)[25]),"=r"((r)[26]),"=r"((r)[27]), \
          "=r"((r)[28]),"=r"((r)[29]),"=r"((r)[30]),"=r"((r)[31]) \
        : "r"(ta))

#define TG_IDESC 0x8200490u
// single-buffered: 6 tiles -> 97KB => 2 CTAs/SM co-resident
#define TG_SMEM  (1024 + 6 * TILE_B)

__device__ __forceinline__ size_t toff(int nwin, int R, int k)
{
    uint32_t inner = (uint32_t)((R & 127) * 128 + (k & 63) * 2);
    inner ^= (inner >> 3) & 0x70;
    return ((size_t)(((R >> 7) * nwin + (k >> 6)) * 3) << 13) + (inner >> 1);
}
__device__ __forceinline__ void wsplit3_t(__nv_bfloat16* base, int nwin, int R, int k, float a)
{
    __nv_bfloat16 h = __float2bfloat16(a);
    float r1 = a - __bfloat162float(h);
    __nv_bfloat16 m = __float2bfloat16(r1);
    float r2 = r1 - __bfloat162float(m);
    size_t o = toff(nwin, R, k);
    base[o] = h;
    base[o + TILE_E] = m;
    base[o + 2 * TILE_E] = __float2bfloat16(r2);
}
__device__ __forceinline__ unsigned long long amax_key(float v, int idx)
{
    unsigned u = __float_as_uint(v);
    u = (u & 0x80000000u) ? ~u : (u | 0x80000000u);
    return ((unsigned long long)u << 32) | (unsigned)(OUTV - idx);
}

// ---------------- batched weight conversion: all 11 jobs, one node --------
#define NWJ 11
struct WJobs {
    const float* W[NWJ];
    long long    off[NWJ];
    int rs[NWJ], co[NWJ], N[NWJ], K[NWJ], nwin[NWJ];
    int b0[NWJ + 1];
};

__global__ void wconv_mega_k(WJobs jb, __nv_bfloat16* __restrict__ base)
{
    const int blk = blockIdx.x;
    int j = 0;
    while (j < NWJ - 1 && blk >= jb.b0[j + 1]) j++;
    const int nwin = jb.nwin[j];
    const int Kp = nwin * 64;
    const int NT = (jb.N[j] + 127) >> 7;
    const size_t tot = (size_t)NT * 128 * Kp;
    size_t i = (size_t)(blk - jb.b0[j]) * 256 + threadIdx.x;
    if (i >= tot) return;
    int R = (int)(i / Kp), k = (int)(i - (size_t)R * Kp);
    float a = (R < jb.N[j] && k < jb.K[j])
            ? jb.W[j][(size_t)R * jb.rs[j] + jb.co[j] + k] : 0.f;
    wsplit3_t(base + jb.off[j], nwin, R, k, a);
}

// ---------------------------------------------------------------------------
// tcgen05 GEMM, TMA-bulk staged, single-buffered, intra-window split-load
// pipelining: segs 0-2 depend only on {A0,A1,A2,B0} (barrier ld0); B1,B2
// arrive under barrier ld1 overlapping the first 12 MMAs. Accumulation
// order unchanged (bit-exact vs R16). M<=64: half-A staging.
// amax=1: fused per-row argmax via atomicMax into g_amax.
// ---------------------------------------------------------------------------
struct TG {
    const __nv_bfloat16* Ab;
    const __nv_bfloat16* Wb;
    const float* bias;
    float* C;
    int M, N, nwin, split, amax;
};

__global__ void __launch_bounds__(128) tgemm_k(TG g0, TG g1, int ua)
{
#if defined(__CUDA_ARCH_FEAT_SM103_ALL)
    const int u = blockIdx.x;
    const TG g = (u < ua) ? g0 : g1;
    int v = (u < ua) ? u : u - ua;
    const int ntn = (g.N + 127) >> 7;
    const int z = v % g.split;
    const int rest = v / g.split;
    const int nt = rest % ntn;
    const int mt = rest / ntn;
    const int nwin = g.nwin;
    const int kcw = (nwin + g.split - 1) / g.split;
    const int w0 = z * kcw;
    int w1 = w0 + kcw; if (w1 > nwin) w1 = nwin;
    const int nw = (w1 > w0) ? (w1 - w0) : 0;
    const int m0 = mt << 7, n0 = nt << 7;
    const bool fin = (g.split == 1);
    float* Cz = g.C + (size_t)z * g.M * g.N;

    const int tid = threadIdx.x;
    const int wid = tid >> 5, lane = tid & 31;
    const int ha = (g.M <= 64) ? 1 : 0;          // half-A staging
    const uint32_t abytes = ha ? 8192u : 16384u;

    extern __shared__ __align__(16) char dyn[];
    const uint32_t dbase = (su32(dyn) + 1023u) & ~1023u;

    __shared__ __align__(8) unsigned long long s_bar[3];  // ld0, ld1, mm
    __shared__ uint32_t s_tptr;

    if (wid == 0) {
        asm volatile("tcgen05.alloc.cta_group::1.sync.aligned.shared::cta.b32 [%0], %1;"
                     :: "r"(su32(&s_tptr)), "r"(128u) : "memory");
        asm volatile("tcgen05.relinquish_alloc_permit.cta_group::1.sync.aligned;");
    }
    if (tid == 0) {
        mbar_init(su32(&s_bar[0]), 1);
        mbar_init(su32(&s_bar[1]), 1);
        mbar_init(su32(&s_bar[2]), 1);
    }

    // zero upper halves of the 3 A slots (rows 64-127) when half-staging
    if (ha && nw > 0) {
#pragma unroll
        for (int p = 0; p < 3; p++) {
            uint32_t basea = dbase + (uint32_t)p * TILE_B + 8192u;
            for (uint32_t o = (uint32_t)tid * 16u; o < 8192u; o += 128u * 16u)
                asm volatile("st.shared.v4.b32 [%0], {%1,%1,%1,%1};"
                             :: "r"(basea + o), "r"(0u) : "memory");
        }
        asm volatile("fence.proxy.async.shared::cta;" ::: "memory");
    }
    __syncthreads();
    const uint32_t tmem = s_tptr;

    if (nw > 0 && tid == 0) {
        const uint32_t ld0 = su32(&s_bar[0]);
        const uint32_t ld1 = su32(&s_bar[1]);
        const uint32_t mm  = su32(&s_bar[2]);
        int pl0 = 0, pl1 = 0, pq = 0;
        const char* At = (const char*)g.Ab;
        const char* Bt = (const char*)g.Wb;
        bool first = true;
        const uint32_t tx0 = 3u * abytes + (uint32_t)TILE_B;  // A0,A1,A2,B0
        const uint32_t tx1 = 2u * (uint32_t)TILE_B;           // B1,B2

        for (int i = 0; i < nw; i++) {
            const int w = w0 + i;
            const size_t abase = ((size_t)((mt * nwin + w) * 3)) * TILE_B;
            const size_t bbase = ((size_t)((nt * nwin + w) * 3)) * TILE_B;

            // phase 0: B0 first (lands earliest), then A parts
            expect_tx(ld0, tx0);
            bulk_g2s(dbase + 3u * TILE_B, Bt + bbase, TILE_B, ld0);
#pragma unroll
            for (int p = 0; p < 3; p++)
                bulk_g2s(dbase + (uint32_t)p * TILE_B,
                         At + abase + (size_t)p * TILE_B, abytes, ld0);
            // phase 1: B1, B2 (overlap with first MMAs)
            expect_tx(ld1, tx1);
            bulk_g2s(dbase + 4u * TILE_B, Bt + bbase + (size_t)TILE_B, TILE_B, ld1);
            bulk_g2s(dbase + 5u * TILE_B, Bt + bbase + 2u * (size_t)TILE_B, TILE_B, ld1);

            mbar_wait(ld0, pl0); pl0 ^= 1;
            // segs 0-2: hh(A0,B0), hm(A1,B0), mh(A2,B0)
            {
                uint64_t bd = mkdesc(dbase + 3u * TILE_B);
#pragma unroll
                for (int s = 0; s < 3; s++) {
                    uint64_t ad = mkdesc(dbase + (uint32_t)s * TILE_B);
#pragma unroll
                    for (int q = 0; q < 4; q++) {
                        mma_bf16_ss(tmem, ad + 2 * q, bd + 2 * q, TG_IDESC, first ? 0u : 1u);
                        first = false;
                    }
                }
            }
            mbar_wait(ld1, pl1); pl1 ^= 1;
            // segs 3-5: hl(A0,B1), lh(A1,B1), mm(A0,B2)
            {
                const int sa[3] = {0, 1, 0};
                const int sb[3] = {4, 4, 5};
#pragma unroll
                for (int s = 0; s < 3; s++) {
                    uint64_t ad = mkdesc(dbase + (uint32_t)sa[s] * TILE_B);
                    uint64_t bd = mkdesc(dbase + (uint32_t)sb[s] * TILE_B);
#pragma unroll
                    for (int q = 0; q < 4; q++)
                        mma_bf16_ss(tmem, ad + 2 * q, bd + 2 * q, TG_IDESC, 1u);
                }
            }
            tc_commit(mm);
            mbar_wait(mm, pq); pq ^= 1;   // single buffer: drain before reuse
        }
    }
    __syncthreads();
    asm volatile("tcgen05.fence::after_thread_sync;" ::: "memory");

    // epilogue
    const int r = m0 + wid * 32 + lane;
    if (nw == 0) {
        if (r < g.M)
            for (int c0 = 0; c0 < 128; c0++) {
                int c = n0 + c0;
                if (c < g.N) Cz[(size_t)r * g.N + c] = (fin && g.bias) ? g.bias[c] : 0.f;
            }
    } else {
        float bestv = -1e30f; int besti = 0;
#pragma unroll
        for (int base = 0; base < 128; base += 32) {
            uint32_t regs[32];
            LDTM_X32(regs, tmem + base);
            asm volatile("tcgen05.wait::ld.sync.aligned;" ::: "memory");
            if (r < g.M) {
#pragma unroll
                for (int q = 0; q < 32; q++) {
                    int c = n0 + base + q;
                    if (c < g.N) {
                        float vv = __uint_as_float(regs[q]);
                        if (fin && g.bias) vv += g.bias[c];
                        Cz[(size_t)r * g.N + c] = vv;
                        if (g.amax && (vv > bestv || (vv == bestv && c < besti))) {
                            bestv = vv; besti = c;
                        }
                    }
                }
            }
        }
        if (g.amax && r < g.M)
            atomicMax(&g_amax[r], amax_key(bestv, besti));
    }
    __syncthreads();
    if (wid == 0)
        asm volatile("tcgen05.dealloc.cta_group::1.sync.aligned.b32 %0, %1;"
                     :: "r"(tmem), "r"(128u));
#else
    (void)g0; (void)g1; (void)ua;   // compile-only stub (runtime picks sm_103a cubin)
#endif
}

// ---------------- elementwise / fused kernels ----------------
__global__ void embed_split_k(const float* __restrict__ table, const int* __restrict__ idx,
                              __nv_bfloat16* __restrict__ Ab)
{
    int i = blockIdx.x * blockDim.x + threadIdx.x;
    if (i >= S_LEN * BB * EMBD) return;
    int r = i / EMBD, e = i - r * EMBD;
    wsplit3_t(Ab, NW_EX, r, e, table[(size_t)idx[r] * EMBD + e]);
}

__global__ void gru_gate2_k(const float* __restrict__ gxf, const float* __restrict__ gxb,
                            const float* __restrict__ pf, const float* __restrict__ pb,
                            const float* __restrict__ bhf, const float* __restrict__ bhb,
                            float* __restrict__ hf, float* __restrict__ hb,
                            __nv_bfloat16* __restrict__ Ahf,
                            __nv_bfloat16* __restrict__ Ahb,
                            float* __restrict__ enc,
                            __nv_bfloat16* __restrict__ Aenc,
                            int sf, int sb)
{
    int i = blockIdx.x * blockDim.x + threadIdx.x;
    if (i >= 2 * BB * HIDN) return;
    int dir = (i >= BB * HIDN);
    int ii = dir ? i - BB * HIDN : i;
    int b = ii / HIDN, j = ii - b * HIDN;
    const float* gx = (dir ? gxb : gxf) + (size_t)b * G3;
    const float* phh = dir ? pb : pf;
    const float* bh = dir ? bhb : bhf;
    float* h = dir ? hb : hf;

    float xr = gx[j], xz = gx[HIDN + j], xn = gx[2 * HIDN + j];
    float hr = bh[j], hz = bh[HIDN + j], hn = bh[2 * HIDN + j];
    for (int z = 0; z < 4; z++) {
        const float* q = phh + ((size_t)z * BB + b) * G3;
        hr += q[j]; hz += q[HIDN + j]; hn += q[2 * HIDN + j];
    }
    float r  = 1.f / (1.f + expf(-(xr + hr)));
    float zz = 1.f / (1.f + expf(-(xz + hz)));
    float n  = tanhf(xn + r * hn);
    float h2 = (1.f - zz) * n + zz * h[ii];
    h[ii] = h2;
    wsplit3_t(dir ? Ahb : Ahf, NW_WH, b, j, h2);
    int row = (dir ? sb : sf) * BB + b;
    int col = dir ? HIDN + j : j;
    enc[(size_t)row * E2 + col] = h2;
    wsplit3_t(Aenc, NW_EN, row, col, h2);
}

__global__ void finalize_tanh_hd_k(const float* __restrict__ parts,
                                   const float* __restrict__ bias,
                                   float* __restrict__ hd,
                                   __nv_bfloat16* __restrict__ Ahd)
{
    int i = blockIdx.x * blockDim.x + threadIdx.x;
    if (i >= BB * HIDN) return;
    int b = i / HIDN, j = i - b * HIDN;
    float v = 0.f;
    for (int z = 0; z < 8; z++) v += parts[(size_t)z * BB * HIDN + i];
    v = tanhf(v + bias[j]);
    hd[i] = v;
    wsplit3_t(Ahd, NW_WH, b, j, v);
}

// fused attention: token from trg (t==0) or fused argmax of previous step
__global__ void attention_k(const float* __restrict__ pa,
                            const float* __restrict__ ep,
                            const float* __restrict__ ab,
                            const float* __restrict__ av,
                            const float* __restrict__ enc,
                            const float* __restrict__ demb,
                            const int*   __restrict__ trg, int t,
                            __nv_bfloat16* __restrict__ Ax,
                            __nv_bfloat16* __restrict__ Ami)
{
    const int b = blockIdx.x;
    const int tid = threadIdx.x;
    const int wid = tid >> 5, lane = tid & 31;
    __shared__ float hqs[ATTD];
    __shared__ float al[S_LEN];

    for (int a = tid; a < ATTD; a += 256) {
        float s = 0.f;
#pragma unroll
        for (int z = 0; z < 8; z++) s += pa[((size_t)z * BB + b) * ATTD + a];
        hqs[a] = s;
    }
    __syncthreads();

    for (int s = wid; s < S_LEN; s += 8) {
        const float* eprow = ep + ((size_t)s * BB + b) * ATTD;
        float e = 0.f;
        for (int a = lane; a < ATTD; a += 32)
            e += av[a] * tanhf(hqs[a] + eprow[a] + ab[a]);
#pragma unroll
        for (int o = 16; o; o >>= 1) e += __shfl_down_sync(0xffffffffu, e, o);
        if (lane == 0) al[s] = e;
    }
    __syncthreads();

    if (tid == 0) {
        float m = -1e30f;
        for (int s = 0; s < S_LEN; s++) m = fmaxf(m, al[s]);
        float sum = 0.f;
        for (int s = 0; s < S_LEN; s++) { float e = expf(al[s] - m); al[s] = e; sum += e; }
        float inv = 1.f / sum;
        for (int s = 0; s < S_LEN; s++) al[s] *= inv;
    }
    __syncthreads();

    for (int hc = tid; hc < E2; hc += 256) {
        float c = 0.f;
        for (int s = 0; s < S_LEN; s++)
            c += al[s] * enc[((size_t)s * BB + b) * E2 + hc];
        wsplit3_t(Ax, NW_X, b, EMBD + hc, c);
        wsplit3_t(Ami, NW_MI, b, HIDN + hc, c);
    }
    const int tok = (t == 0) ? trg[b]
                  : (int)(OUTV - (unsigned)(g_amax[b] & 0xffffffffu));
    for (int e = tid; e < EMBD; e += 256) {
        float vv = demb[(size_t)tok * EMBD + e];
        wsplit3_t(Ax, NW_X, b, e, vv);
        wsplit3_t(Ami, NW_MI, b, G3 + e, vv);
    }
}

// decoder GRU gate (8 partials per operand)
__global__ void gru_gate_k(const float* __restrict__ gx, const float* __restrict__ bx,
                           const float* __restrict__ gh, const float* __restrict__ bh,
                           float* __restrict__ h,
                           __nv_bfloat16* __restrict__ Ahd,
                           __nv_bfloat16* __restrict__ Ami)
{
    int i = blockIdx.x * blockDim.x + threadIdx.x;
    if (i >= BB * HIDN) return;
    int b = i / HIDN, j = i - b * HIDN;
    float xr = bx[j], xz = bx[HIDN + j], xn = bx[2 * HIDN + j];
    float hr = bh[j], hz = bh[HIDN + j], hn = bh[2 * HIDN + j];
    for (int z = 0; z < 8; z++) {
        const float* q1 = gx + ((size_t)z * BB + b) * G3;
        const float* q2 = gh + ((size_t)z * BB + b) * G3;
        xr += q1[j]; xz += q1[HIDN + j]; xn += q1[2 * HIDN + j];
        hr += q2[j]; hz += q2[HIDN + j]; hn += q2[2 * HIDN + j];
    }
    float r  = 1.f / (1.f + expf(-(xr + hr)));
    float zz = 1.f / (1.f + expf(-(xz + hz)));
    float n  = tanhf(xn + r * hn);
    float h2 = (1.f - zz) * n + zz * h[i];
    h[i] = h2;
    wsplit3_t(Ahd, NW_WH, b, j, h2);
    wsplit3_t(Ami, NW_MI, b, j, h2);
}

// maxout finalize (16 partials) + zero argmax accumulator
__global__ void finalize_max_k(const float* __restrict__ pm,
                               const float* __restrict__ bias,
                               __nv_bfloat16* __restrict__ Atm)
{
    int i = blockIdx.x * blockDim.x + threadIdx.x;
    if (i < BB) g_amax[i] = 0ull;
    if (i >= BB * MXO) return;
    int b = i / MXO, o = i - b * MXO;
    float v0 = bias[2 * o], v1 = bias[2 * o + 1];
    for (int z = 0; z < 16; z++) {
        const float* q = pm + ((size_t)z * BB + b) * MX2;
        v0 += q[2 * o]; v1 += q[2 * o + 1];
    }
    wsplit3_t(Atm, NW_TM, b, o, fmaxf(v0, v1));
}

// ---------------- host ----------------
static inline int up(int n, int b) { return (n + b - 1) / b; }

static inline TG mkt(const __nv_bfloat16* Ab, const __nv_bfloat16* Wb,
                     const float* bias, float* C, int M, int N, int nwin,
                     int split, int amax = 0)
{
    TG g; g.Ab = Ab; g.Wb = Wb; g.bias = bias; g.C = C;
    g.M = M; g.N = N; g.nwin = nwin; g.split = split; g.amax = amax;
    return g;
}
static inline int units(const TG& g)
{
    return ((g.M + 127) >> 7) * ((g.N + 127) >> 7) * g.split;
}
static inline void tg1(const TG& g)
{
    tgemm_k<<<units(g), 128, TG_SMEM>>>(g, g, units(g));
}
static inline void tg2(const TG& a, const TG& b)
{
    tgemm_k<<<units(a) + units(b), 128, TG_SMEM>>>(a, b, units(a));
}

extern "C" void kernel_launch(void* const* d_in, const int* in_sizes, int n_in,
                              void* d_out, int out_size)
{
    (void)in_sizes; (void)n_in; (void)out_size;
    const int*   src      = (const int*)  d_in[0];
    const int*   trg      = (const int*)  d_in[1];
    const float* enc_emb  = (const float*)d_in[2];
    const float* enc_wx_f = (const float*)d_in[3];
    const float* enc_wh_f = (const float*)d_in[4];
    const float* enc_bx_f = (const float*)d_in[5];
    const float* enc_bh_f = (const float*)d_in[6];
    const float* enc_wx_b = (const float*)d_in[7];
    const float* enc_wh_b = (const float*)d_in[8];
    const float* enc_bx_b = (const float*)d_in[9];
    const float* enc_bh_b = (const float*)d_in[10];
    const float* enc_fc_w = (const float*)d_in[11];
    const float* enc_fc_b = (const float*)d_in[12];
    const float* attn_w   = (const float*)d_in[13];
    const float* attn_b   = (const float*)d_in[14];
    const float* attn_v   = (const float*)d_in[15];
    const float* dec_emb  = (const float*)d_in[16];
    const float* dec_wx   = (const float*)d_in[17];
    const float* dec_wh   = (const float*)d_in[18];
    const float* dec_bx   = (const float*)d_in[19];
    const float* dec_bh   = (const float*)d_in[20];
    const float* max_w    = (const float*)d_in[21];
    const float* max_b    = (const float*)d_in[22];
    const float* out_w    = (const float*)d_in[23];
    const float* out_b    = (const float*)d_in[24];

    cudaFuncSetAttribute(tgemm_k, cudaFuncAttributeMaxDynamicSharedMemorySize, TG_SMEM);

    float* ws = nullptr;
    __nv_bfloat16* wb = nullptr; __nv_bfloat16* abx = nullptr;
    cudaGetSymbolAddress((void**)&ws, g_ws);
    cudaGetSymbolAddress((void**)&wb, g_wb);
    cudaGetSymbolAddress((void**)&abx, g_ab);

    float* gxf = ws + O_GXF;
    float* gxb = ws + O_GXB;
    float* enc = ws + O_ENC;
    float* ep  = ws + O_EP;
    float* pa  = ws + O_PA;
    float* pb  = ws + O_PB;
    float* pm  = ws + O_PM;
    float* hf  = ws + O_HF;
    float* hb  = ws + O_HB;
    float* hd  = ws + O_HD;
    float* out = (float*)d_out;

    __nv_bfloat16* Aemb = abx + AB_EMB;
    __nv_bfloat16* Aenc = abx + AB_ENC;
    __nv_bfloat16* Ahf  = abx + AB_HF;
    __nv_bfloat16* Ahb  = abx + AB_HB;
    __nv_bfloat16* Ahd  = abx + AB_HD;
    __nv_bfloat16* Ax   = abx + AB_X;
    __nv_bfloat16* Ami  = abx + AB_MI;
    __nv_bfloat16* Atm  = abx + AB_TM;

    // batched weight conversion: one node for all 11 weights
    {
        WJobs jb;
        const float* Ws[NWJ]  = {enc_wx_f, enc_wx_b, enc_wh_f, enc_wh_b, enc_fc_w,
                                 attn_w, attn_w, dec_wx, dec_wh, max_w, out_w};
        const long long off[NWJ] = {(long long)WB_EXF, (long long)WB_EXB,
                                    (long long)WB_WHF, (long long)WB_WHB,
                                    (long long)WB_FC,  (long long)WB_AWH,
                                    (long long)WB_AWE, (long long)WB_DWX,
                                    (long long)WB_DWH, (long long)WB_MXW,
                                    (long long)WB_OUW};
        const int rs[NWJ]   = {EMBD, EMBD, HIDN, HIDN, HIDN, G3, G3, DXK, HIDN, MXK, MXO};
        const int co[NWJ]   = {0, 0, 0, 0, 0, 0, HIDN, 0, 0, 0, 0};
        const int Nn[NWJ]   = {3000, 3000, 3000, 3000, 1000, 1000, 1000, 3000, 3000, 1000, 30000};
        const int Kk[NWJ]   = {EMBD, EMBD, HIDN, HIDN, HIDN, HIDN, E2, DXK, HIDN, MXK, MXO};
        const int nw[NWJ]   = {NW_EX, NW_EX, NW_WH, NW_WH, NW_WH, NW_WH, NW_EN,
                               NW_X, NW_WH, NW_MI, NW_TM};
        int bacc = 0;
        for (int j = 0; j < NWJ; j++) {
            jb.W[j] = Ws[j]; jb.off[j] = off[j];
            jb.rs[j] = rs[j]; jb.co[j] = co[j];
            jb.N[j] = Nn[j]; jb.K[j] = Kk[j]; jb.nwin[j] = nw[j];
            jb.b0[j] = bacc;
            size_t tot = (size_t)(((Nn[j] + 127) >> 7) * 128) * (size_t)nw[j] * 64;
            bacc += (int)((tot + 255) / 256);
        }
        jb.b0[NWJ] = bacc;
        wconv_mega_k<<<bacc, 256>>>(jb, wb);
    }

    cudaMemsetAsync(abx, 0, AB_TOT * sizeof(__nv_bfloat16));
    cudaMemsetAsync(hf, 0, (size_t)2 * BB * HIDN * sizeof(float));  // hf+hb adjacent
    cudaMemsetAsync(out, 0, (size_t)BB * OUTV * sizeof(float));

    // ---------------- Encoder ----------------
    embed_split_k<<<up(S_LEN * BB * EMBD, 256), 256>>>(enc_emb, src, Aemb);
    tg2(mkt(Aemb, wb + WB_EXF, enc_bx_f, gxf, S_LEN * BB, G3, NW_EX, 1),
        mkt(Aemb, wb + WB_EXB, enc_bx_b, gxb, S_LEN * BB, G3, NW_EX, 1));

    for (int s = 0; s < S_LEN; s++) {
        int sb = S_LEN - 1 - s;
        tg2(mkt(Ahf, wb + WB_WHF, nullptr, pa, BB, G3, NW_WH, 4),
            mkt(Ahb, wb + WB_WHB, nullptr, pb, BB, G3, NW_WH, 4));
        gru_gate2_k<<<up(2 * BB * HIDN, 256), 256>>>(
            gxf + (size_t)s * BB * G3, gxb + (size_t)sb * BB * G3,
            pa, pb, enc_bh_f, enc_bh_b, hf, hb, Ahf, Ahb, enc, Aenc, s, sb);
    }

    tg1(mkt(Ahb, wb + WB_FC, nullptr, pa, BB, HIDN, NW_WH, 8));
    finalize_tanh_hd_k<<<up(BB * HIDN, 256), 256>>>(pa, enc_fc_b, hd, Ahd);
    // e_part + initial hq (dual)
    tg2(mkt(Aenc, wb + WB_AWE, nullptr, ep, S_LEN * BB, ATTD, NW_EN, 1),
        mkt(Ahd, wb + WB_AWH, nullptr, pa, BB, ATTD, NW_WH, 8));

    // ---------------- Decoder ----------------
    for (int t = 0; t < T_LEN - 1; t++) {
        attention_k<<<BB, 256>>>(pa, ep, attn_b, attn_v, enc, dec_emb, trg, t, Ax, Ami);
        // dec dual GEMM: split 8 each
        tg2(mkt(Ax,  wb + WB_DWX, nullptr, pa, BB, G3, NW_X,  8),
            mkt(Ahd, wb + WB_DWH, nullptr, pb, BB, G3, NW_WH, 8));
        gru_gate_k<<<up(BB * HIDN, 256), 256>>>(pa, dec_bx, pb, dec_bh, hd, Ahd, Ami);
        // maxout split 16 + next-step hq split 8 (dual)
        tg2(mkt(Ami, wb + WB_MXW, nullptr, pm, BB, MX2, NW_MI, 16),
            mkt(Ahd, wb + WB_AWH, nullptr, pa, BB, ATTD, NW_WH, 8));
        finalize_max_k<<<up(BB * MXO, 256), 256>>>(pm, max_b, Atm);
        float* pred = out + (size_t)(t + 1) * BB * OUTV;
        tg1(mkt(Atm, wb + WB_OUW, out_b, pred, BB, OUTV, NW_TM, 1, 1));
    }
}